// round 1
// baseline (speedup 1.0000x reference)
#include <cuda_runtime.h>

#define Hh 128
#define Ww 128
#define HW 16384
#define C 128
#define KK 9
#define EPS 1e-5f

// ---------------- scratch (device globals; no runtime alloc) ----------------
__device__ float g_bufA[HW*C];
__device__ float g_bufB[HW*C];
__device__ float g_pre[HW*C];
__device__ float g_offs[HW*18];
__device__ float g_maskb[HW*9];
__device__ float g_wt[2][KK*C*C];      // [k][ci][co] transposed conv weights
__device__ float g_effwT[2][KK*C*32];  // [k][ci][j<32] folded offset/mask weights
__device__ float g_effb[2][32];
__device__ float g_sum[C];
__device__ float g_sumsq[C];

// ---------------- prep: transpose conv weights ----------------
__global__ void prep_wt_kernel(const float* __restrict__ cw0, const float* __restrict__ cw1){
    int idx = blockIdx.x*blockDim.x + threadIdx.x;
    if (idx >= KK*C*C) return;
    int k = idx/(C*C); int r = idx - k*C*C; int ci = r>>7; int co = r&127;
    g_wt[0][idx] = cw0[(co*C+ci)*KK + k];
    g_wt[1][idx] = cw1[(co*C+ci)*KK + k];
}

// ---------------- prep: fold ow/mw through cw ----------------
__global__ void prep_eff_kernel(const float* __restrict__ cw, const float* __restrict__ ow,
                                const float* __restrict__ mw, const float* __restrict__ cb, int b){
    int idx = blockIdx.x*blockDim.x + threadIdx.x;
    if (idx >= KK*C*32) return;
    int k = idx/(C*32); int r = idx - k*C*32; int ci = r>>5; int j = r&31;
    float s = 0.f;
    if (j < 27){
        const float* P = (j<18) ? (ow + j*C) : (mw + (j-18)*C);
        const float* wk = cw + ci*KK + k;
        for (int co=0; co<C; co++) s += P[co]*wk[co*C*KK];
    }
    g_effwT[b][idx] = s;
    if (idx < 32){
        float bbv = 0.f;
        if (idx < 27){
            const float* P = (idx<18) ? (ow + idx*C) : (mw + (idx-18)*C);
            for (int co=0; co<C; co++) bbv += P[co]*cb[co];
        }
        g_effb[b][idx] = bbv;
    }
}

// ---------------- 27-channel folded conv -> offsets + softmax(mask) ----------------
__global__ __launch_bounds__(256) void offcv_kernel(const float* __restrict__ x, int b){
    __shared__ float As[64*132];   // [px][ci], stride 132 (16B-mult, conflict-free)
    __shared__ float Bs[64*32];    // [ciLocal][j]
    const int tid = threadIdx.x;
    const int pb = blockIdx.x*64;
    const int h0 = pb >> 7;
    const int w0 = pb & 127;
    const int lp = tid >> 2, q = tid & 3;   // lp = pixel (0..63), q = ci quarter / j-group
    float acc[8];
#pragma unroll
    for (int j=0;j<8;j++) acc[j]=0.f;

    for (int k=0;k<KK;k++){
        int ky = k/3 - 1, kx = k - (k/3)*3 - 1;
        int hh = h0 + ky;
        {
            int wwp = w0 + lp + kx;
            bool vr = (hh>=0) & (hh<Hh) & (wwp>=0) & (wwp<Ww);
            float4* dst = (float4*)(As + lp*132 + q*32);
            if (vr){
                const float4* src = (const float4*)(x + (((hh<<7)+wwp)<<7) + q*32);
#pragma unroll
                for (int i=0;i<8;i++) dst[i] = src[i];
            } else {
                float4 z = make_float4(0.f,0.f,0.f,0.f);
#pragma unroll
                for (int i=0;i<8;i++) dst[i] = z;
            }
        }
        for (int cc=0; cc<2; cc++){
            __syncthreads();
            const float* s = &g_effwT[b][(k*C + cc*64)*32];
#pragma unroll
            for (int t=0;t<8;t++) Bs[tid + t*256] = s[tid + t*256];
            __syncthreads();
            const float* Arow = As + lp*132 + cc*64;
#pragma unroll 8
            for (int ci=0; ci<64; ci++){
                float a = Arow[ci];
                const float* Brow = Bs + ci*32 + q*8;
#pragma unroll
                for (int j=0;j<8;j++) acc[j] += a * Brow[j];
            }
            __syncthreads();
        }
    }
    // stage results per pixel, then offsets + softmax
    float* Vs = As;  // alias (stride 33)
#pragma unroll
    for (int j=0;j<8;j++) Vs[lp*33 + q*8 + j] = acc[j] + g_effb[b][q*8+j];
    __syncthreads();
    if (tid < 64){
        int p = pb + tid;
        const float* v = Vs + tid*33;
#pragma unroll
        for (int j=0;j<18;j++) g_offs[p*18+j] = v[j];
        float mx = v[18];
#pragma unroll
        for (int j=19;j<27;j++) mx = fmaxf(mx, v[j]);
        float e[9]; float sm = 0.f;
#pragma unroll
        for (int j=0;j<9;j++){ e[j] = expf(v[18+j]-mx); sm += e[j]; }
        float inv = 1.f/sm;
#pragma unroll
        for (int j=0;j<9;j++) g_maskb[p*9+j] = e[j]*inv;
    }
}

// ---------------- bilinear sample + mask + 128x1152 GEMM + bias ----------------
__global__ __launch_bounds__(256) void samplegemm_kernel(const float* __restrict__ x,
                                                         const float* __restrict__ cb, int b){
    __shared__ float As[64*132];   // sampled [px][ci] for current tap
    __shared__ float Bs[16*128];   // weights [ciLocal][co]
    const int tid = threadIdx.x;
    const int pb = blockIdx.x*64;
    const int h0 = pb >> 7;
    const int w0 = pb & 127;
    const int lp = tid >> 2, q = tid & 3;      // build roles
    const int pid = tid >> 4, cid = tid & 15;  // accumulate roles: 4 px, 8 co per thread
    float acc[4][8];
#pragma unroll
    for (int i=0;i<4;i++)
#pragma unroll
        for (int j=0;j<8;j++) acc[i][j]=0.f;

    for (int k=0;k<KK;k++){
        {   // build sampled tile (4 threads per pixel, 32 ch each)
            int p = pb + lp;
            float offy = g_offs[p*18 + 2*k];
            float offx = g_offs[p*18 + 2*k + 1];
            float m = g_maskb[p*9 + k];
            float py = (float)(h0 - 1 + k/3) + offy;
            float px = (float)(w0 + lp - 1 + (k - (k/3)*3)) + offx;
            float y0f = floorf(py), x0f = floorf(px);
            int y0 = (int)y0f, x0i = (int)x0f;
            float wy1 = py - y0f, wy0v = 1.f - wy1;
            float wx1 = px - x0f, wx0v = 1.f - wx1;
            int y1 = y0+1, x1i = x0i+1;
            bool vy0 = (y0>=0)&(y0<Hh), vy1 = (y1>=0)&(y1<Hh);
            bool vx0 = (x0i>=0)&(x0i<Ww), vx1 = (x1i>=0)&(x1i<Ww);
            float w00 = (vy0&&vx0)? wy0v*wx0v : 0.f;
            float w01 = (vy0&&vx1)? wy0v*wx1 : 0.f;
            float w10 = (vy1&&vx0)? wy1*wx0v : 0.f;
            float w11 = (vy1&&vx1)? wy1*wx1 : 0.f;
            int y0c = min(max(y0,0),Hh-1), y1c = min(max(y1,0),Hh-1);
            int x0c = min(max(x0i,0),Ww-1), x1c = min(max(x1i,0),Ww-1);
            const float4* r00 = (const float4*)(x + (((y0c<<7)+x0c)<<7) + q*32);
            const float4* r01 = (const float4*)(x + (((y0c<<7)+x1c)<<7) + q*32);
            const float4* r10 = (const float4*)(x + (((y1c<<7)+x0c)<<7) + q*32);
            const float4* r11 = (const float4*)(x + (((y1c<<7)+x1c)<<7) + q*32);
            float4* dst = (float4*)(As + lp*132 + q*32);
#pragma unroll
            for (int i=0;i<8;i++){
                float4 a = r00[i], bq = r01[i], c4 = r10[i], d4 = r11[i];
                float4 o;
                o.x = m*(w00*a.x + w01*bq.x + w10*c4.x + w11*d4.x);
                o.y = m*(w00*a.y + w01*bq.y + w10*c4.y + w11*d4.y);
                o.z = m*(w00*a.z + w01*bq.z + w10*c4.z + w11*d4.z);
                o.w = m*(w00*a.w + w01*bq.w + w10*c4.w + w11*d4.w);
                dst[i] = o;
            }
        }
        const float* wtk = &g_wt[b][k*C*C];
        for (int cc=0; cc<8; cc++){
            __syncthreads();
            const float* s = wtk + cc*16*C;
#pragma unroll
            for (int t=0;t<8;t++) Bs[tid + t*256] = s[tid + t*256];
            __syncthreads();
            const float* Ab = As + (pid*4)*132 + cc*16;
#pragma unroll
            for (int ci=0; ci<16; ci++){
                float a0 = Ab[ci], a1 = Ab[132+ci], a2 = Ab[264+ci], a3 = Ab[396+ci];
                const float4* Br = (const float4*)(Bs + ci*C + cid*8);
                float4 b0 = Br[0], b1 = Br[1];
                float bv[8] = {b0.x,b0.y,b0.z,b0.w,b1.x,b1.y,b1.z,b1.w};
#pragma unroll
                for (int j=0;j<8;j++){
                    acc[0][j] += a0*bv[j];
                    acc[1][j] += a1*bv[j];
                    acc[2][j] += a2*bv[j];
                    acc[3][j] += a3*bv[j];
                }
            }
            __syncthreads();
        }
    }
    // epilogue: bias + store (NHWC)
    int co0 = cid*8;
    float4 bias0 = *(const float4*)(cb + co0);
    float4 bias1 = *(const float4*)(cb + co0 + 4);
    float bvv[8] = {bias0.x,bias0.y,bias0.z,bias0.w,bias1.x,bias1.y,bias1.z,bias1.w};
#pragma unroll
    for (int i=0;i<4;i++){
        int p = pb + pid*4 + i;
        float4 o0 = make_float4(acc[i][0]+bvv[0], acc[i][1]+bvv[1], acc[i][2]+bvv[2], acc[i][3]+bvv[3]);
        float4 o1 = make_float4(acc[i][4]+bvv[4], acc[i][5]+bvv[5], acc[i][6]+bvv[6], acc[i][7]+bvv[7]);
        *(float4*)(g_pre + p*C + co0) = o0;
        *(float4*)(g_pre + p*C + co0 + 4) = o1;
    }
}

// ---------------- instance-norm helpers ----------------
__global__ void zerosum_kernel(){
    int t = threadIdx.x;
    if (t < C){ g_sum[t]=0.f; g_sumsq[t]=0.f; }
}

__global__ __launch_bounds__(128) void reduce_kernel(){
    int c = threadIdx.x;
    int p0 = blockIdx.x * 128;
    float s=0.f, sq=0.f;
    for (int i=0;i<128;i++){
        float v = g_pre[(p0+i)*C + c];
        s += v; sq += v*v;
    }
    atomicAdd(&g_sum[c], s);
    atomicAdd(&g_sumsq[c], sq);
}

__global__ void normrelu_kernel(const float* __restrict__ bg, const float* __restrict__ bb,
                                float* __restrict__ out){
    int idx = blockIdx.x*blockDim.x + threadIdx.x;
    int c = idx & 127;
    float mu = g_sum[c] * (1.f/HW);
    float var = g_sumsq[c] * (1.f/HW) - mu*mu;
    float v = (g_pre[idx]-mu)*rsqrtf(var+EPS)*bg[c] + bb[c];
    out[idx] = fmaxf(v, 0.f);
}

// ---------------- projections (optionally dual-source) ----------------
__global__ __launch_bounds__(256) void proj_kernel(const float* __restrict__ xa, const float* __restrict__ wa,
        const float* __restrict__ xb, const float* __restrict__ wb, float* __restrict__ out, int nco){
    __shared__ float As[64*35];
    __shared__ float Bs[128*35];
    const int tid = threadIdx.x;
    const int pb = blockIdx.x*64;
    const int cbase = blockIdx.y*128;
    const int pid = tid >> 4, cid = tid & 15;
    float acc[4][8];
#pragma unroll
    for (int i=0;i<4;i++)
#pragma unroll
        for (int j=0;j<8;j++) acc[i][j]=0.f;

    int nsrc = (xb != nullptr) ? 2 : 1;
    for (int s=0; s<nsrc; s++){
        const float* xs = s ? xb : xa;
        const float* ws = s ? wb : wa;
        for (int cc=0; cc<4; cc++){
            __syncthreads();
#pragma unroll
            for (int t=0;t<8;t++){
                int idx = tid + t*256;
                int px = idx >> 5, ci = idx & 31;
                As[px*35 + ci] = xs[(pb+px)*C + cc*32 + ci];
            }
#pragma unroll
            for (int t=0;t<16;t++){
                int idx = tid + t*256;
                int co = idx >> 5, ci = idx & 31;
                int cog = cbase + co;
                Bs[co*35 + ci] = (cog < nco) ? ws[cog*C + cc*32 + ci] : 0.f;
            }
            __syncthreads();
#pragma unroll 4
            for (int ci=0; ci<32; ci++){
                float a0 = As[(pid*4+0)*35+ci], a1 = As[(pid*4+1)*35+ci];
                float a2 = As[(pid*4+2)*35+ci], a3 = As[(pid*4+3)*35+ci];
#pragma unroll
                for (int j=0;j<8;j++){
                    float bvv = Bs[(cid + 16*j)*35 + ci];
                    acc[0][j] += a0*bvv;
                    acc[1][j] += a1*bvv;
                    acc[2][j] += a2*bvv;
                    acc[3][j] += a3*bvv;
                }
            }
        }
    }
#pragma unroll
    for (int j=0;j<8;j++){
        int co = cbase + cid + 16*j;
        if (co < nco){
#pragma unroll
            for (int i=0;i<4;i++){
                out[(size_t)co*HW + pb + pid*4 + i] = acc[i][j];
            }
        }
    }
}

// ---------------- final layernorm over W ----------------
__global__ __launch_bounds__(128) void ln_kernel(float* __restrict__ o, const float* __restrict__ lnw,
                                                 const float* __restrict__ lnb){
    __shared__ float ss[4], ssq[4];
    int row = blockIdx.x;
    float* r = o + (size_t)row*128;
    int t = threadIdx.x;
    float v = r[t];
    float s = v, sq = v*v;
#pragma unroll
    for (int off=16; off; off>>=1){
        s  += __shfl_down_sync(0xffffffffu, s, off);
        sq += __shfl_down_sync(0xffffffffu, sq, off);
    }
    int wid = t >> 5, lane = t & 31;
    if (lane==0){ ss[wid]=s; ssq[wid]=sq; }
    __syncthreads();
    float S  = ss[0]+ss[1]+ss[2]+ss[3];
    float SQ = ssq[0]+ssq[1]+ssq[2]+ssq[3];
    float mu = S*(1.f/128.f);
    float var = SQ*(1.f/128.f) - mu*mu;
    r[t] = (v-mu)*rsqrtf(var+EPS)*lnw[t] + lnb[t];
}

// ---------------- host orchestration ----------------
extern "C" void kernel_launch(void* const* d_in, const int* in_sizes, int n_in,
                              void* d_out, int out_size){
    (void)in_sizes; (void)n_in; (void)out_size;
    const float* x[5];
    for (int i=0;i<5;i++) x[i] = (const float*)d_in[i];
    const float* cw[2] = {(const float*)d_in[5],  (const float*)d_in[11]};
    const float* cb[2] = {(const float*)d_in[6],  (const float*)d_in[12]};
    const float* ow[2] = {(const float*)d_in[7],  (const float*)d_in[13]};
    const float* mw[2] = {(const float*)d_in[8],  (const float*)d_in[14]};
    const float* bg[2] = {(const float*)d_in[9],  (const float*)d_in[15]};
    const float* bb[2] = {(const float*)d_in[10], (const float*)d_in[16]};
    const float* pwa[5] = {(const float*)d_in[17], (const float*)d_in[18], (const float*)d_in[19],
                           (const float*)d_in[21], (const float*)d_in[23]};
    const float* pwb[5] = {nullptr, nullptr, (const float*)d_in[20],
                           (const float*)d_in[22], (const float*)d_in[24]};
    const float* lnw = (const float*)d_in[25];
    const float* lnb = (const float*)d_in[26];
    float* outp = (float*)d_out;

    float *pA=nullptr, *pB=nullptr;
    cudaGetSymbolAddress((void**)&pA, g_bufA);
    cudaGetSymbolAddress((void**)&pB, g_bufB);

    prep_wt_kernel<<<(KK*C*C+255)/256, 256>>>(cw[0], cw[1]);
    prep_eff_kernel<<<(KK*C*32+255)/256, 256>>>(cw[0], ow[0], mw[0], cb[0], 0);
    prep_eff_kernel<<<(KK*C*32+255)/256, 256>>>(cw[1], ow[1], mw[1], cb[1], 1);

    const int ncos[5] = {20,80,150,210,308};
    const int coff[5] = {0,20,100,250,460};
    for (int i=0;i<5;i++){
        const float* cur = x[i];
        // deform block 1
        offcv_kernel<<<256,256>>>(cur, 0);
        zerosum_kernel<<<1,128>>>();
        samplegemm_kernel<<<256,256>>>(cur, cb[0], 0);
        reduce_kernel<<<128,128>>>();
        normrelu_kernel<<<HW*C/256,256>>>(bg[0], bb[0], pA);
        // deform block 2
        offcv_kernel<<<256,256>>>(pA, 1);
        zerosum_kernel<<<1,128>>>();
        samplegemm_kernel<<<256,256>>>(pA, cb[1], 1);
        reduce_kernel<<<128,128>>>();
        normrelu_kernel<<<HW*C/256,256>>>(bg[1], bb[1], pB);
        // projection(s)
        dim3 g(HW/64, (ncos[i]+127)/128);
        proj_kernel<<<g, 256>>>(pB, pwa[i], (i>=2) ? cur : nullptr, pwb[i],
                                outp + (size_t)coff[i]*HW, ncos[i]);
    }
    ln_kernel<<<768*Hh, 128>>>(outp, lnw, lnb);
}

// round 2
// speedup vs baseline: 1.1529x; 1.1529x over previous
#include <cuda_runtime.h>

#define Hh 128
#define Ww 128
#define HW 16384
#define C 128
#define KK 9
#define EPS 1e-5f

// ---------------- scratch (device globals; no runtime alloc) ----------------
__device__ float g_bufA[HW*C];
__device__ float g_bufB[HW*C];
__device__ float g_pre[HW*C];
__device__ float g_offs[HW*18];
__device__ float g_maskb[HW*9];
__device__ float g_wt[2][KK*C*C];      // [k][ci][co]
__device__ float g_effwT[2][KK*C*32];  // [k][ci][j<32]
__device__ float g_effb[2][32];
__device__ float g_sum[C];
__device__ float g_sumsq[C];

// ---------------- prep: transpose conv weights ----------------
__global__ void prep_wt_kernel(const float* __restrict__ cw0, const float* __restrict__ cw1){
    int idx = blockIdx.x*blockDim.x + threadIdx.x;
    if (idx >= KK*C*C) return;
    int k = idx/(C*C); int r = idx - k*C*C; int ci = r>>7; int co = r&127;
    g_wt[0][idx] = cw0[(co*C+ci)*KK + k];
    g_wt[1][idx] = cw1[(co*C+ci)*KK + k];
}

// ---------------- prep: fold ow/mw through cw ----------------
__global__ void prep_eff_kernel(const float* __restrict__ cw, const float* __restrict__ ow,
                                const float* __restrict__ mw, const float* __restrict__ cb, int b){
    int idx = blockIdx.x*blockDim.x + threadIdx.x;
    if (idx >= KK*C*32) return;
    int k = idx/(C*32); int r = idx - k*C*32; int ci = r>>5; int j = r&31;
    float s = 0.f;
    if (j < 27){
        const float* P = (j<18) ? (ow + j*C) : (mw + (j-18)*C);
        const float* wk = cw + ci*KK + k;
        for (int co=0; co<C; co++) s += P[co]*wk[co*C*KK];
    }
    g_effwT[b][idx] = s;
    if (idx < 32){
        float bbv = 0.f;
        if (idx < 27){
            const float* P = (idx<18) ? (ow + idx*C) : (mw + (idx-18)*C);
            for (int co=0; co<C; co++) bbv += P[co]*cb[co];
        }
        g_effb[b][idx] = bbv;
    }
}

// ---------------- 27-out folded conv -> offsets + softmax(mask) ----------------
// grid 128 (one block per image row), 256 threads. Tile: 128px x 32j.
// Per thread: 4px x 4j. smem dyn: As[128*132] + Bs[128*32]
__global__ __launch_bounds__(256) void offcv2_kernel(const float* __restrict__ x, int b){
    extern __shared__ float sm[];
    float* As = sm;             // 128*132
    float* Bs = sm + 128*132;   // 128*32
    const int tid = threadIdx.x;
    const int h0 = blockIdx.x;
    const int pb = h0*128;
    const int lp = tid >> 1, q = tid & 1;   // build: 2 thr/px, 64 ch each
    const int pid = tid >> 3, jg = tid & 7; // compute: px group (4), j group (4)
    float acc[4][4];
#pragma unroll
    for (int i=0;i<4;i++)
#pragma unroll
        for (int j=0;j<4;j++) acc[i][j]=0.f;

    for (int k=0;k<KK;k++){
        __syncthreads();
        {   // build shifted row tile
            int ky = k/3 - 1, kx = k - (k/3)*3 - 1;
            int hh = h0 + ky;
            int wwp = lp + kx;
            bool vr = (hh>=0) & (hh<Hh) & (wwp>=0) & (wwp<Ww);
            float4* dst = (float4*)(As + lp*132 + q*64);
            if (vr){
                const float4* src = (const float4*)(x + (((hh<<7)+wwp)<<7) + q*64);
#pragma unroll
                for (int i=0;i<16;i++) dst[i] = src[i];
            } else {
                float4 z = make_float4(0.f,0.f,0.f,0.f);
#pragma unroll
                for (int i=0;i<16;i++) dst[i] = z;
            }
        }
        {   // load Bs: 128ci x 32j
            const float* wsrc = &g_effwT[b][k*C*32];
#pragma unroll
            for (int t=0;t<16;t++) Bs[tid + t*256] = wsrc[tid + t*256];
        }
        __syncthreads();
        // compute
#pragma unroll 4
        for (int ci4=0; ci4<32; ci4++){
            float4 a[4];
#pragma unroll
            for (int i=0;i<4;i++) a[i] = *(const float4*)(As + (pid*4+i)*132 + ci4*4);
            const float* ap = (const float*)a;
#pragma unroll
            for (int u=0;u<4;u++){
                float4 bq = *(const float4*)(Bs + (ci4*4+u)*32 + jg*4);
                float bvv[4] = {bq.x,bq.y,bq.z,bq.w};
#pragma unroll
                for (int i=0;i<4;i++)
#pragma unroll
                    for (int j=0;j<4;j++) acc[i][j] += ap[i*4+u]*bvv[j];
            }
        }
    }
    // epilogue
    __syncthreads();
    float* Vs = As;  // [128][33]
#pragma unroll
    for (int i=0;i<4;i++)
#pragma unroll
        for (int j=0;j<4;j++) Vs[(pid*4+i)*33 + jg*4+j] = acc[i][j] + g_effb[b][jg*4+j];
    __syncthreads();
    if (tid < 128){
        int p = pb + tid;
        const float* v = Vs + tid*33;
#pragma unroll
        for (int j=0;j<18;j++) g_offs[p*18+j] = v[j];
        float mx = v[18];
#pragma unroll
        for (int j=19;j<27;j++) mx = fmaxf(mx, v[j]);
        float e[9]; float smv = 0.f;
#pragma unroll
        for (int j=0;j<9;j++){ e[j] = expf(v[18+j]-mx); smv += e[j]; }
        float inv = 1.f/smv;
#pragma unroll
        for (int j=0;j<9;j++) g_maskb[p*9+j] = e[j]*inv;
    }
}

// ---------------- bilinear sample + mask + GEMM + bias + fused stats ----------------
// grid 128, 512 threads. Tile: 128px x 128co. Per thread: 4px x 8co.
// smem dyn: As[128*132] + Bs[32*128]
__global__ __launch_bounds__(512) void samplegemm2_kernel(const float* __restrict__ x,
                                                          const float* __restrict__ cb, int b){
    extern __shared__ float sm[];
    float* As = sm;             // 128*132
    float* Bs = sm + 128*132;   // 32*128
    const int tid = threadIdx.x;
    const int h0 = blockIdx.x;
    const int pb = h0*128;
    const int lp = tid >> 2, q = tid & 3;     // build: 4 thr/px, 32 ch each
    const int pid = tid >> 4, cid = tid & 15; // compute: 32 px-groups x 16 co-groups
    float acc[4][8];
#pragma unroll
    for (int i=0;i<4;i++)
#pragma unroll
        for (int j=0;j<8;j++) acc[i][j]=0.f;

    for (int k=0;k<KK;k++){
        __syncthreads();
        {   // build sampled tile
            int p = pb + lp;
            float offy = g_offs[p*18 + 2*k];
            float offx = g_offs[p*18 + 2*k + 1];
            float m = g_maskb[p*9 + k];
            float py = (float)(h0 - 1 + k/3) + offy;
            float pxf = (float)(lp - 1 + (k - (k/3)*3)) + offx;
            float y0f = floorf(py), x0f = floorf(pxf);
            int y0 = (int)y0f, x0i = (int)x0f;
            float wy1 = py - y0f, wy0v = 1.f - wy1;
            float wx1 = pxf - x0f, wx0v = 1.f - wx1;
            int y1 = y0+1, x1i = x0i+1;
            bool vy0 = (y0>=0)&(y0<Hh), vy1 = (y1>=0)&(y1<Hh);
            bool vx0 = (x0i>=0)&(x0i<Ww), vx1 = (x1i>=0)&(x1i<Ww);
            float w00 = (vy0&&vx0)? wy0v*wx0v : 0.f;
            float w01 = (vy0&&vx1)? wy0v*wx1 : 0.f;
            float w10 = (vy1&&vx0)? wy1*wx0v : 0.f;
            float w11 = (vy1&&vx1)? wy1*wx1 : 0.f;
            int y0c = min(max(y0,0),Hh-1), y1c = min(max(y1,0),Hh-1);
            int x0c = min(max(x0i,0),Ww-1), x1c = min(max(x1i,0),Ww-1);
            const float4* r00 = (const float4*)(x + (((y0c<<7)+x0c)<<7) + q*32);
            const float4* r01 = (const float4*)(x + (((y0c<<7)+x1c)<<7) + q*32);
            const float4* r10 = (const float4*)(x + (((y1c<<7)+x0c)<<7) + q*32);
            const float4* r11 = (const float4*)(x + (((y1c<<7)+x1c)<<7) + q*32);
            float4* dst = (float4*)(As + lp*132 + q*32);
#pragma unroll
            for (int i=0;i<8;i++){
                float4 a = r00[i], bq = r01[i], c4 = r10[i], d4 = r11[i];
                float4 o;
                o.x = m*(w00*a.x + w01*bq.x + w10*c4.x + w11*d4.x);
                o.y = m*(w00*a.y + w01*bq.y + w10*c4.y + w11*d4.y);
                o.z = m*(w00*a.z + w01*bq.z + w10*c4.z + w11*d4.z);
                o.w = m*(w00*a.w + w01*bq.w + w10*c4.w + w11*d4.w);
                dst[i] = o;
            }
        }
        const float* wtk = &g_wt[b][k*C*C];
        for (int cc=0; cc<4; cc++){
            __syncthreads();
            {   // load Bs: 32ci x 128co
                const float* s = wtk + cc*32*C;
#pragma unroll
                for (int t=0;t<8;t++) Bs[tid + t*512] = s[tid + t*512];
            }
            __syncthreads();
#pragma unroll
            for (int ci4=0; ci4<8; ci4++){
                float4 a[4];
#pragma unroll
                for (int i=0;i<4;i++) a[i] = *(const float4*)(As + (pid*4+i)*132 + cc*32 + ci4*4);
                const float* ap = (const float*)a;
#pragma unroll
                for (int u=0;u<4;u++){
                    float4 b0 = *(const float4*)(Bs + (ci4*4+u)*128 + cid*8);
                    float4 b1 = *(const float4*)(Bs + (ci4*4+u)*128 + cid*8 + 4);
                    float bvv[8] = {b0.x,b0.y,b0.z,b0.w,b1.x,b1.y,b1.z,b1.w};
#pragma unroll
                    for (int i=0;i<4;i++)
#pragma unroll
                        for (int j=0;j<8;j++) acc[i][j] += ap[i*4+u]*bvv[j];
                }
            }
        }
    }
    // epilogue: bias + store + fused per-channel stats
    __syncthreads();   // done reading As/Bs
    int co0 = cid*8;
    float4 bias0 = *(const float4*)(cb + co0);
    float4 bias1 = *(const float4*)(cb + co0 + 4);
    float bvv[8] = {bias0.x,bias0.y,bias0.z,bias0.w,bias1.x,bias1.y,bias1.z,bias1.w};
    float psum[8], psq[8];
#pragma unroll
    for (int j=0;j<8;j++){ psum[j]=0.f; psq[j]=0.f; }
#pragma unroll
    for (int i=0;i<4;i++){
        int p = pb + pid*4 + i;
        float v0=acc[i][0]+bvv[0], v1=acc[i][1]+bvv[1], v2=acc[i][2]+bvv[2], v3=acc[i][3]+bvv[3];
        float v4=acc[i][4]+bvv[4], v5=acc[i][5]+bvv[5], v6=acc[i][6]+bvv[6], v7=acc[i][7]+bvv[7];
        *(float4*)(g_pre + p*C + co0)     = make_float4(v0,v1,v2,v3);
        *(float4*)(g_pre + p*C + co0 + 4) = make_float4(v4,v5,v6,v7);
        psum[0]+=v0; psum[1]+=v1; psum[2]+=v2; psum[3]+=v3;
        psum[4]+=v4; psum[5]+=v5; psum[6]+=v6; psum[7]+=v7;
        psq[0]+=v0*v0; psq[1]+=v1*v1; psq[2]+=v2*v2; psq[3]+=v3*v3;
        psq[4]+=v4*v4; psq[5]+=v5*v5; psq[6]+=v6*v6; psq[7]+=v7*v7;
    }
    float* Rs1 = Bs;   // 32 groups x 128 co = 4096 floats
    float* Rs2 = As;   // reuse
#pragma unroll
    for (int j=0;j<8;j++){
        Rs1[pid*128 + co0 + j] = psum[j];
        Rs2[pid*128 + co0 + j] = psq[j];
    }
    __syncthreads();
    if (tid < 128){
        float S=0.f, Q=0.f;
#pragma unroll
        for (int g=0; g<32; g++){ S += Rs1[g*128+tid]; Q += Rs2[g*128+tid]; }
        atomicAdd(&g_sum[tid], S);
        atomicAdd(&g_sumsq[tid], Q);
    }
}

// ---------------- instance-norm helpers ----------------
__global__ void zerosum_kernel(){
    int t = threadIdx.x;
    if (t < C){ g_sum[t]=0.f; g_sumsq[t]=0.f; }
}

__global__ void normrelu_kernel(const float* __restrict__ bg, const float* __restrict__ bb,
                                float* __restrict__ out){
    int idx = blockIdx.x*blockDim.x + threadIdx.x;
    int c = idx & 127;
    float mu = g_sum[c] * (1.f/HW);
    float var = g_sumsq[c] * (1.f/HW) - mu*mu;
    float v = (g_pre[idx]-mu)*rsqrtf(var+EPS)*bg[c] + bb[c];
    out[idx] = fmaxf(v, 0.f);
}

// ---------------- projections ----------------
// grid (128, co tiles), 256 threads. Tile 128px x 128co, per thread 8px x 8co.
__global__ __launch_bounds__(256) void proj2_kernel(const float* __restrict__ xa, const float* __restrict__ wa,
        const float* __restrict__ xb, const float* __restrict__ wb, float* __restrict__ out, int nco){
    __shared__ float As[128*36];
    __shared__ float Bs[32*128];
    const int tid = threadIdx.x;
    const int pb = blockIdx.x*128;
    const int cbase = blockIdx.y*128;
    const int pid = tid >> 4, cid = tid & 15;
    float acc[8][8];
#pragma unroll
    for (int i=0;i<8;i++)
#pragma unroll
        for (int j=0;j<8;j++) acc[i][j]=0.f;

    int nsrc = (xb != nullptr) ? 2 : 1;
    for (int s=0; s<nsrc; s++){
        const float* xs = s ? xb : xa;
        const float* ws = s ? wb : wa;
        for (int cc=0; cc<4; cc++){
            __syncthreads();
#pragma unroll
            for (int t=0;t<16;t++){
                int idx = tid + t*256;
                int px = idx >> 5, ci = idx & 31;
                As[px*36 + ci] = xs[(pb+px)*C + cc*32 + ci];
            }
#pragma unroll
            for (int t=0;t<16;t++){
                int idx = tid + t*256;
                int ci = idx >> 7, co = idx & 127;
                int cog = cbase + co;
                Bs[ci*128 + co] = (cog < nco) ? ws[cog*C + cc*32 + ci] : 0.f;
            }
            __syncthreads();
#pragma unroll
            for (int ci4=0; ci4<8; ci4++){
                float4 a[8];
#pragma unroll
                for (int i=0;i<8;i++) a[i] = *(const float4*)(As + (pid*8+i)*36 + ci4*4);
                const float* ap = (const float*)a;
#pragma unroll
                for (int u=0;u<4;u++){
                    float4 b0 = *(const float4*)(Bs + (ci4*4+u)*128 + cid*8);
                    float4 b1 = *(const float4*)(Bs + (ci4*4+u)*128 + cid*8 + 4);
                    float bvv[8] = {b0.x,b0.y,b0.z,b0.w,b1.x,b1.y,b1.z,b1.w};
#pragma unroll
                    for (int i=0;i<8;i++)
#pragma unroll
                        for (int j=0;j<8;j++) acc[i][j] += ap[i*4+u]*bvv[j];
                }
            }
        }
    }
#pragma unroll
    for (int j=0;j<8;j++){
        int co = cbase + cid*8 + j;
        if (co < nco){
            float4 o0 = make_float4(acc[0][j],acc[1][j],acc[2][j],acc[3][j]);
            float4 o1 = make_float4(acc[4][j],acc[5][j],acc[6][j],acc[7][j]);
            float* dst = out + (size_t)co*HW + pb + pid*8;
            *(float4*)dst = o0;
            *(float4*)(dst+4) = o1;
        }
    }
}

// ---------------- final layernorm over W ----------------
__global__ __launch_bounds__(128) void ln_kernel(float* __restrict__ o, const float* __restrict__ lnw,
                                                 const float* __restrict__ lnb){
    __shared__ float ss[4], ssq[4];
    int row = blockIdx.x;
    float* r = o + (size_t)row*128;
    int t = threadIdx.x;
    float v = r[t];
    float s = v, sq = v*v;
#pragma unroll
    for (int off=16; off; off>>=1){
        s  += __shfl_down_sync(0xffffffffu, s, off);
        sq += __shfl_down_sync(0xffffffffu, sq, off);
    }
    int wid = t >> 5, lane = t & 31;
    if (lane==0){ ss[wid]=s; ssq[wid]=sq; }
    __syncthreads();
    float S  = ss[0]+ss[1]+ss[2]+ss[3];
    float SQ = ssq[0]+ssq[1]+ssq[2]+ssq[3];
    float mu = S*(1.f/128.f);
    float var = SQ*(1.f/128.f) - mu*mu;
    r[t] = (v-mu)*rsqrtf(var+EPS)*lnw[t] + lnb[t];
}

// ---------------- host orchestration ----------------
#define BIG_SMEM (128*132*4 + 32*128*4)   // 83968 B

extern "C" void kernel_launch(void* const* d_in, const int* in_sizes, int n_in,
                              void* d_out, int out_size){
    (void)in_sizes; (void)n_in; (void)out_size;
    const float* x[5];
    for (int i=0;i<5;i++) x[i] = (const float*)d_in[i];
    const float* cw[2] = {(const float*)d_in[5],  (const float*)d_in[11]};
    const float* cb[2] = {(const float*)d_in[6],  (const float*)d_in[12]};
    const float* ow[2] = {(const float*)d_in[7],  (const float*)d_in[13]};
    const float* mw[2] = {(const float*)d_in[8],  (const float*)d_in[14]};
    const float* bg[2] = {(const float*)d_in[9],  (const float*)d_in[15]};
    const float* bb[2] = {(const float*)d_in[10], (const float*)d_in[16]};
    const float* pwa[5] = {(const float*)d_in[17], (const float*)d_in[18], (const float*)d_in[19],
                           (const float*)d_in[21], (const float*)d_in[23]};
    const float* pwb[5] = {nullptr, nullptr, (const float*)d_in[20],
                           (const float*)d_in[22], (const float*)d_in[24]};
    const float* lnw = (const float*)d_in[25];
    const float* lnb = (const float*)d_in[26];
    float* outp = (float*)d_out;

    float *pA=nullptr, *pB=nullptr;
    cudaGetSymbolAddress((void**)&pA, g_bufA);
    cudaGetSymbolAddress((void**)&pB, g_bufB);

    cudaFuncSetAttribute(offcv2_kernel, cudaFuncAttributeMaxDynamicSharedMemorySize, BIG_SMEM);
    cudaFuncSetAttribute(samplegemm2_kernel, cudaFuncAttributeMaxDynamicSharedMemorySize, BIG_SMEM);

    prep_wt_kernel<<<(KK*C*C+255)/256, 256>>>(cw[0], cw[1]);
    prep_eff_kernel<<<(KK*C*32+255)/256, 256>>>(cw[0], ow[0], mw[0], cb[0], 0);
    prep_eff_kernel<<<(KK*C*32+255)/256, 256>>>(cw[1], ow[1], mw[1], cb[1], 1);

    const int ncos[5] = {20,80,150,210,308};
    const int coff[5] = {0,20,100,250,460};
    for (int i=0;i<5;i++){
        const float* cur = x[i];
        // deform block 1
        offcv2_kernel<<<128,256,BIG_SMEM>>>(cur, 0);
        zerosum_kernel<<<1,128>>>();
        samplegemm2_kernel<<<128,512,BIG_SMEM>>>(cur, cb[0], 0);
        normrelu_kernel<<<HW*C/256,256>>>(bg[0], bb[0], pA);
        // deform block 2
        offcv2_kernel<<<128,256,BIG_SMEM>>>(pA, 1);
        zerosum_kernel<<<1,128>>>();
        samplegemm2_kernel<<<128,512,BIG_SMEM>>>(pA, cb[1], 1);
        normrelu_kernel<<<HW*C/256,256>>>(bg[1], bb[1], pB);
        // projection(s)
        dim3 g(HW/128, (ncos[i]+127)/128);
        proj2_kernel<<<g, 256>>>(pB, pwa[i], (i>=2) ? cur : nullptr, pwb[i],
                                 outp + (size_t)coff[i]*HW, ncos[i]);
    }
    ln_kernel<<<768*Hh, 128>>>(outp, lnw, lnb);
}

// round 5
// speedup vs baseline: 1.7097x; 1.4830x over previous
#include <cuda_runtime.h>
#include <cstdint>

#define Hh 128
#define Ww 128
#define HW 16384
#define C 128
#define KK 9
#define EPS 1e-5f

// ---------------- scratch (device globals; no runtime alloc) ----------------
__device__ float g_bufA[HW*C];
__device__ float g_bufB[HW*C];
__device__ float g_pre[HW*C];
__device__ float g_offs[HW*18];
__device__ float g_maskb[HW*9];
__device__ float g_wtBh[2][KK*C*C];    // [k][ci][co]  tf32-hi
__device__ float g_wtBl[2][KK*C*C];    // [k][ci][co]  tf32-lo
__device__ float g_effwT[2][KK*C*32];  // [k][ci][j<32]
__device__ float g_effb[2][32];
__device__ float g_sum[C];
__device__ float g_sumsq[C];

__device__ __forceinline__ float tf32_rn(float a){
    float r; asm("cvt.rna.tf32.f32 %0, %1;" : "=f"(r) : "f"(a)); return r;
}
__device__ __forceinline__ void mma_tf32(float* d, uint32_t a0,uint32_t a1,uint32_t a2,uint32_t a3,
                                         uint32_t b0, uint32_t b1){
    asm volatile("mma.sync.aligned.m16n8k8.row.col.f32.tf32.tf32.f32 "
        "{%0,%1,%2,%3}, {%4,%5,%6,%7}, {%8,%9}, {%0,%1,%2,%3};"
        : "+f"(d[0]),"+f"(d[1]),"+f"(d[2]),"+f"(d[3])
        : "r"(a0),"r"(a1),"r"(a2),"r"(a3),"r"(b0),"r"(b1));
}

// ---------------- prep kernels ----------------
__global__ void prep_wtsplit_kernel(const float* __restrict__ cw0, const float* __restrict__ cw1){
    int idx = blockIdx.x*blockDim.x + threadIdx.x;
    if (idx >= KK*C*C) return;
    int k = idx/(C*C); int r = idx - k*C*C; int ci = r>>7; int co = r&127;
    float w0 = cw0[(co*C+ci)*KK + k];
    float w1 = cw1[(co*C+ci)*KK + k];
    float h0 = tf32_rn(w0), h1 = tf32_rn(w1);
    g_wtBh[0][idx] = h0; g_wtBl[0][idx] = tf32_rn(w0 - h0);
    g_wtBh[1][idx] = h1; g_wtBl[1][idx] = tf32_rn(w1 - h1);
}

__global__ void prep_eff_kernel(const float* __restrict__ cw, const float* __restrict__ ow,
                                const float* __restrict__ mw, const float* __restrict__ cb, int b){
    int idx = blockIdx.x*blockDim.x + threadIdx.x;
    if (idx >= KK*C*32) return;
    int k = idx/(C*32); int r = idx - k*C*32; int ci = r>>5; int j = r&31;
    float s = 0.f;
    if (j < 27){
        const float* P = (j<18) ? (ow + j*C) : (mw + (j-18)*C);
        const float* wk = cw + ci*KK + k;
        for (int co=0; co<C; co++) s += P[co]*wk[co*C*KK];
    }
    g_effwT[b][idx] = s;
    if (idx < 32){
        float bbv = 0.f;
        if (idx < 27){
            const float* P = (idx<18) ? (ow + idx*C) : (mw + (idx-18)*C);
            for (int co=0; co<C; co++) bbv += P[co]*cb[co];
        }
        g_effb[b][idx] = bbv;
    }
}

// ---------------- 27-out folded conv -> offsets + softmax(mask) ----------------
__global__ __launch_bounds__(256) void offcv2_kernel(const float* __restrict__ x, int b){
    extern __shared__ float sm[];
    float* As = sm;             // 128*132
    float* Bs = sm + 128*132;   // 128*32
    const int tid = threadIdx.x;
    const int h0 = blockIdx.x;
    const int pb = h0*128;
    const int lp = tid >> 1, q = tid & 1;
    const int pid = tid >> 3, jg = tid & 7;
    float acc[4][4];
#pragma unroll
    for (int i=0;i<4;i++)
#pragma unroll
        for (int j=0;j<4;j++) acc[i][j]=0.f;

    for (int k=0;k<KK;k++){
        __syncthreads();
        {
            int ky = k/3 - 1, kx = k - (k/3)*3 - 1;
            int hh = h0 + ky;
            int wwp = lp + kx;
            bool vr = (hh>=0) & (hh<Hh) & (wwp>=0) & (wwp<Ww);
            float4* dst = (float4*)(As + lp*132 + q*64);
            if (vr){
                const float4* src = (const float4*)(x + (((hh<<7)+wwp)<<7) + q*64);
#pragma unroll
                for (int i=0;i<16;i++) dst[i] = src[i];
            } else {
                float4 z = make_float4(0.f,0.f,0.f,0.f);
#pragma unroll
                for (int i=0;i<16;i++) dst[i] = z;
            }
        }
        {
            const float* wsrc = &g_effwT[b][k*C*32];
#pragma unroll
            for (int t=0;t<16;t++) Bs[tid + t*256] = wsrc[tid + t*256];
        }
        __syncthreads();
#pragma unroll 4
        for (int ci4=0; ci4<32; ci4++){
            float4 a[4];
#pragma unroll
            for (int i=0;i<4;i++) a[i] = *(const float4*)(As + (pid*4+i)*132 + ci4*4);
            const float* ap = (const float*)a;
#pragma unroll
            for (int u=0;u<4;u++){
                float4 bq = *(const float4*)(Bs + (ci4*4+u)*32 + jg*4);
                float bvv[4] = {bq.x,bq.y,bq.z,bq.w};
#pragma unroll
                for (int i=0;i<4;i++)
#pragma unroll
                    for (int j=0;j<4;j++) acc[i][j] += ap[i*4+u]*bvv[j];
            }
        }
    }
    __syncthreads();
    float* Vs = As;
#pragma unroll
    for (int i=0;i<4;i++)
#pragma unroll
        for (int j=0;j<4;j++) Vs[(pid*4+i)*33 + jg*4+j] = acc[i][j] + g_effb[b][jg*4+j];
    __syncthreads();
    if (tid < 128){
        int p = pb + tid;
        const float* v = Vs + tid*33;
#pragma unroll
        for (int j=0;j<18;j++) g_offs[p*18+j] = v[j];
        float mx = v[18];
#pragma unroll
        for (int j=19;j<27;j++) mx = fmaxf(mx, v[j]);
        float e[9]; float smv = 0.f;
#pragma unroll
        for (int j=0;j<9;j++){ e[j] = expf(v[18+j]-mx); smv += e[j]; }
        float inv = 1.f/smv;
#pragma unroll
        for (int j=0;j<9;j++) g_maskb[p*9+j] = e[j]*inv;
    }
}

// ---------------- mma.sync tf32-split sample-GEMM ----------------
// grid 128 (one per image row), 256 threads = 8 warps.
// Block tile 128px x 128co; warp tile 32px x 64co; 3xTF32 split.
// smem floats: AS_H[128*36] AS_L[128*36] BS_H[32*136] BS_L[32*136] = 17920 f
#define AS_H 0
#define AS_L 4608
#define BS_H 9216
#define BS_L 13568
#define SG_SMEM (17920*4)

__global__ __launch_bounds__(256) void samplegemm4_kernel(const float* __restrict__ x,
                                                          const float* __restrict__ cb, int b){
    extern __shared__ float sm[];
    const int tid = threadIdx.x;
    const int h0 = blockIdx.x;
    const int pb = h0*128;
    const int lp = tid >> 1, q = tid & 1;        // build roles: 2 thr/px, 16 ci each
    const int wid = tid >> 5, lane = tid & 31;
    const int warpM = wid & 3, warpN = wid >> 2; // 4 x 2 warp grid
    const int lg = lane >> 2, lc = lane & 3;     // lane group / thread-in-group

    const uint32_t* AsHu = (const uint32_t*)(sm + AS_H);
    const uint32_t* AsLu = (const uint32_t*)(sm + AS_L);
    const uint32_t* BsHu = (const uint32_t*)(sm + BS_H);
    const uint32_t* BsLu = (const uint32_t*)(sm + BS_L);

    float d[2][8][4];
#pragma unroll
    for (int mt=0;mt<2;mt++)
#pragma unroll
        for (int nt=0;nt<8;nt++)
#pragma unroll
            for (int i=0;i<4;i++) d[mt][nt][i]=0.f;

    for (int k=0;k<KK;k++){
        // per-pixel sampling params for tap k
        int p = pb + lp;
        float offy = g_offs[p*18 + 2*k];
        float offx = g_offs[p*18 + 2*k + 1];
        float m = g_maskb[p*9 + k];
        float py = (float)(h0 - 1 + k/3) + offy;
        float pxf = (float)(lp - 1 + (k - (k/3)*3)) + offx;
        float y0f = floorf(py), x0f = floorf(pxf);
        int y0 = (int)y0f, x0i = (int)x0f;
        float wy1 = py - y0f, wy0v = 1.f - wy1;
        float wx1 = pxf - x0f, wx0v = 1.f - wx1;
        int y1 = y0+1, x1i = x0i+1;
        bool vy0 = (y0>=0)&(y0<Hh), vy1 = (y1>=0)&(y1<Hh);
        bool vx0 = (x0i>=0)&(x0i<Ww), vx1 = (x1i>=0)&(x1i<Ww);
        float w00 = (vy0&&vx0)? wy0v*wx0v : 0.f;
        float w01 = (vy0&&vx1)? wy0v*wx1 : 0.f;
        float w10 = (vy1&&vx0)? wy1*wx0v : 0.f;
        float w11 = (vy1&&vx1)? wy1*wx1 : 0.f;
        int y0c = min(max(y0,0),Hh-1), y1c = min(max(y1,0),Hh-1);
        int x0c = min(max(x0i,0),Ww-1), x1c = min(max(x1i,0),Ww-1);
        const float* base00 = x + (((y0c<<7)+x0c)<<7);
        const float* base01 = x + (((y0c<<7)+x1c)<<7);
        const float* base10 = x + (((y1c<<7)+x0c)<<7);
        const float* base11 = x + (((y1c<<7)+x1c)<<7);

        for (int cc=0; cc<4; cc++){       // 32-ci chunks
            __syncthreads();              // previous chunk's mma done
            // ---- build A hi/lo: px lp, chunk-local ci q*16..q*16+15
            {
                int cg = cc*32 + q*16;
                const float4* r00 = (const float4*)(base00 + cg);
                const float4* r01 = (const float4*)(base01 + cg);
                const float4* r10 = (const float4*)(base10 + cg);
                const float4* r11 = (const float4*)(base11 + cg);
                float* dH = sm + AS_H + lp*36 + q*16;
                float* dL = sm + AS_L + lp*36 + q*16;
#pragma unroll
                for (int i=0;i<4;i++){
                    float4 a = r00[i], bq = r01[i], c4 = r10[i], e4 = r11[i];
                    float4 o;
                    o.x = m*(w00*a.x + w01*bq.x + w10*c4.x + w11*e4.x);
                    o.y = m*(w00*a.y + w01*bq.y + w10*c4.y + w11*e4.y);
                    o.z = m*(w00*a.z + w01*bq.z + w10*c4.z + w11*e4.z);
                    o.w = m*(w00*a.w + w01*bq.w + w10*c4.w + w11*e4.w);
                    float4 hi, lo;
                    hi.x = tf32_rn(o.x); lo.x = tf32_rn(o.x - hi.x);
                    hi.y = tf32_rn(o.y); lo.y = tf32_rn(o.y - hi.y);
                    hi.z = tf32_rn(o.z); lo.z = tf32_rn(o.z - hi.z);
                    hi.w = tf32_rn(o.w); lo.w = tf32_rn(o.w - hi.w);
                    *(float4*)(dH + i*4) = hi;
                    *(float4*)(dL + i*4) = lo;
                }
            }
            // ---- copy B hi/lo chunk: [32ci][128co], stride 136
            {
                const float* srcH = &g_wtBh[b][k*C*C + cc*32*C];
                const float* srcL = &g_wtBl[b][k*C*C + cc*32*C];
#pragma unroll
                for (int t=0;t<16;t++){
                    int idx = tid + t*256;
                    int ci = idx >> 7, co = idx & 127;
                    sm[BS_H + ci*136 + co] = srcH[idx];
                    sm[BS_L + ci*136 + co] = srcL[idx];
                }
            }
            __syncthreads();
            // ---- mma: 4 k-steps x (2 mt x 8 nt x 3 passes)
#pragma unroll
            for (int ks=0; ks<4; ks++){
                int kc = ks*8;
                uint32_t ah[2][4], al[2][4];
#pragma unroll
                for (int mt=0;mt<2;mt++){
                    int r0 = warpM*32 + mt*16 + lg;
                    int c0 = kc + lc;
                    ah[mt][0] = AsHu[r0*36 + c0];
                    ah[mt][1] = AsHu[(r0+8)*36 + c0];
                    ah[mt][2] = AsHu[r0*36 + c0 + 4];
                    ah[mt][3] = AsHu[(r0+8)*36 + c0 + 4];
                    al[mt][0] = AsLu[r0*36 + c0];
                    al[mt][1] = AsLu[(r0+8)*36 + c0];
                    al[mt][2] = AsLu[r0*36 + c0 + 4];
                    al[mt][3] = AsLu[(r0+8)*36 + c0 + 4];
                }
#pragma unroll
                for (int nt=0;nt<8;nt++){
                    int cn = warpN*64 + nt*8 + lg;
                    uint32_t bh0 = BsHu[(kc+lc)*136 + cn];
                    uint32_t bh1 = BsHu[(kc+4+lc)*136 + cn];
                    uint32_t bl0 = BsLu[(kc+lc)*136 + cn];
                    uint32_t bl1 = BsLu[(kc+4+lc)*136 + cn];
                    mma_tf32(d[0][nt], ah[0][0],ah[0][1],ah[0][2],ah[0][3], bh0,bh1);
                    mma_tf32(d[1][nt], ah[1][0],ah[1][1],ah[1][2],ah[1][3], bh0,bh1);
                    mma_tf32(d[0][nt], ah[0][0],ah[0][1],ah[0][2],ah[0][3], bl0,bl1);
                    mma_tf32(d[1][nt], ah[1][0],ah[1][1],ah[1][2],ah[1][3], bl0,bl1);
                    mma_tf32(d[0][nt], al[0][0],al[0][1],al[0][2],al[0][3], bh0,bh1);
                    mma_tf32(d[1][nt], al[1][0],al[1][1],al[1][2],al[1][3], bh0,bh1);
                }
            }
        }
    }

    // ---------------- epilogue: regs -> Vs (+bias) -> g_pre + fused stats ----------------
    __syncthreads();
    float* Vs = sm;               // [128][132], overlaps A/B buffers
    float* Ps  = sm + 16896;      // [2][128]
    float* Ps2 = sm + 17152;      // [2][128]
#pragma unroll
    for (int mt=0;mt<2;mt++){
        int r0 = warpM*32 + mt*16 + lg;
#pragma unroll
        for (int nt=0;nt<8;nt++){
            int co0 = warpN*64 + nt*8 + lc*2;
            float b0v = cb[co0], b1v = cb[co0+1];
            *(float2*)(Vs + r0*132 + co0)     = make_float2(d[mt][nt][0]+b0v, d[mt][nt][1]+b1v);
            *(float2*)(Vs + (r0+8)*132 + co0) = make_float2(d[mt][nt][2]+b0v, d[mt][nt][3]+b1v);
        }
    }
    __syncthreads();
    // write to g_pre (coalesced)
#pragma unroll
    for (int t=0;t<64;t++){
        int idx = tid + t*256;
        int px = idx >> 7, co = idx & 127;
        g_pre[(pb+px)*C + co] = Vs[px*132 + co];
    }
    // fused per-channel stats
    {
        int co = tid & 127, qq = tid >> 7;
        float S = 0.f, Q = 0.f;
#pragma unroll 8
        for (int i=0;i<64;i++){
            float v = Vs[(qq*64+i)*132 + co];
            S += v; Q += v*v;
        }
        Ps[qq*128 + co] = S;
        Ps2[qq*128 + co] = Q;
        __syncthreads();
        if (tid < 128){
            atomicAdd(&g_sum[tid],  Ps[tid] + Ps[128+tid]);
            atomicAdd(&g_sumsq[tid], Ps2[tid] + Ps2[128+tid]);
        }
    }
}

// ---------------- instance-norm helpers ----------------
__global__ void zerosum_kernel(){
    int t = threadIdx.x;
    if (t < C){ g_sum[t]=0.f; g_sumsq[t]=0.f; }
}

__global__ void normrelu_kernel(const float* __restrict__ bg, const float* __restrict__ bb,
                                float* __restrict__ out){
    int idx = blockIdx.x*blockDim.x + threadIdx.x;
    int c = idx & 127;
    float mu = g_sum[c] * (1.f/HW);
    float var = g_sumsq[c] * (1.f/HW) - mu*mu;
    float v = (g_pre[idx]-mu)*rsqrtf(var+EPS)*bg[c] + bb[c];
    out[idx] = fmaxf(v, 0.f);
}

// ---------------- projections (SIMT fp32) ----------------
__global__ __launch_bounds__(256) void proj2_kernel(const float* __restrict__ xa, const float* __restrict__ wa,
        const float* __restrict__ xb, const float* __restrict__ wb, float* __restrict__ out, int nco){
    __shared__ float As[128*36];
    __shared__ float Bs[32*128];
    const int tid = threadIdx.x;
    const int pb = blockIdx.x*128;
    const int cbase = blockIdx.y*128;
    const int pid = tid >> 4, cid = tid & 15;
    float acc[8][8];
#pragma unroll
    for (int i=0;i<8;i++)
#pragma unroll
        for (int j=0;j<8;j++) acc[i][j]=0.f;

    int nsrc = (xb != nullptr) ? 2 : 1;
    for (int s=0; s<nsrc; s++){
        const float* xs = s ? xb : xa;
        const float* ws = s ? wb : wa;
        for (int cc=0; cc<4; cc++){
            __syncthreads();
#pragma unroll
            for (int t=0;t<16;t++){
                int idx = tid + t*256;
                int px = idx >> 5, ci = idx & 31;
                As[px*36 + ci] = xs[(pb+px)*C + cc*32 + ci];
            }
#pragma unroll
            for (int t=0;t<16;t++){
                int idx = tid + t*256;
                int ci = idx >> 7, co = idx & 127;
                int cog = cbase + co;
                Bs[ci*128 + co] = (cog < nco) ? ws[cog*C + cc*32 + ci] : 0.f;
            }
            __syncthreads();
#pragma unroll
            for (int ci4=0; ci4<8; ci4++){
                float4 a[8];
#pragma unroll
                for (int i=0;i<8;i++) a[i] = *(const float4*)(As + (pid*8+i)*36 + ci4*4);
                const float* ap = (const float*)a;
#pragma unroll
                for (int u=0;u<4;u++){
                    float4 b0 = *(const float4*)(Bs + (ci4*4+u)*128 + cid*8);
                    float4 b1 = *(const float4*)(Bs + (ci4*4+u)*128 + cid*8 + 4);
                    float bvv[8] = {b0.x,b0.y,b0.z,b0.w,b1.x,b1.y,b1.z,b1.w};
#pragma unroll
                    for (int i=0;i<8;i++)
#pragma unroll
                        for (int j=0;j<8;j++) acc[i][j] += ap[i*4+u]*bvv[j];
                }
            }
        }
    }
#pragma unroll
    for (int j=0;j<8;j++){
        int co = cbase + cid*8 + j;
        if (co < nco){
            float4 o0 = make_float4(acc[0][j],acc[1][j],acc[2][j],acc[3][j]);
            float4 o1 = make_float4(acc[4][j],acc[5][j],acc[6][j],acc[7][j]);
            float* dst = out + (size_t)co*HW + pb + pid*8;
            *(float4*)dst = o0;
            *(float4*)(dst+4) = o1;
        }
    }
}

// ---------------- final layernorm over W ----------------
__global__ __launch_bounds__(128) void ln_kernel(float* __restrict__ o, const float* __restrict__ lnw,
                                                 const float* __restrict__ lnb){
    __shared__ float ss[4], ssq[4];
    int row = blockIdx.x;
    float* r = o + (size_t)row*128;
    int t = threadIdx.x;
    float v = r[t];
    float s = v, sq = v*v;
#pragma unroll
    for (int off=16; off; off>>=1){
        s  += __shfl_down_sync(0xffffffffu, s, off);
        sq += __shfl_down_sync(0xffffffffu, sq, off);
    }
    int wid = t >> 5, lane = t & 31;
    if (lane==0){ ss[wid]=s; ssq[wid]=sq; }
    __syncthreads();
    float S  = ss[0]+ss[1]+ss[2]+ss[3];
    float SQ = ssq[0]+ssq[1]+ssq[2]+ssq[3];
    float mu = S*(1.f/128.f);
    float var = SQ*(1.f/128.f) - mu*mu;
    r[t] = (v-mu)*rsqrtf(var+EPS)*lnw[t] + lnb[t];
}

// ---------------- host orchestration ----------------
#define OFF_SMEM (128*132*4 + 128*32*4)

extern "C" void kernel_launch(void* const* d_in, const int* in_sizes, int n_in,
                              void* d_out, int out_size){
    (void)in_sizes; (void)n_in; (void)out_size;
    const float* x[5];
    for (int i=0;i<5;i++) x[i] = (const float*)d_in[i];
    const float* cw[2] = {(const float*)d_in[5],  (const float*)d_in[11]};
    const float* cb[2] = {(const float*)d_in[6],  (const float*)d_in[12]};
    const float* ow[2] = {(const float*)d_in[7],  (const float*)d_in[13]};
    const float* mw[2] = {(const float*)d_in[8],  (const float*)d_in[14]};
    const float* bg[2] = {(const float*)d_in[9],  (const float*)d_in[15]};
    const float* bb[2] = {(const float*)d_in[10], (const float*)d_in[16]};
    const float* pwa[5] = {(const float*)d_in[17], (const float*)d_in[18], (const float*)d_in[19],
                           (const float*)d_in[21], (const float*)d_in[23]};
    const float* pwb[5] = {nullptr, nullptr, (const float*)d_in[20],
                           (const float*)d_in[22], (const float*)d_in[24]};
    const float* lnw = (const float*)d_in[25];
    const float* lnb = (const float*)d_in[26];
    float* outp = (float*)d_out;

    float *pA=nullptr, *pB=nullptr;
    cudaGetSymbolAddress((void**)&pA, g_bufA);
    cudaGetSymbolAddress((void**)&pB, g_bufB);

    cudaFuncSetAttribute(offcv2_kernel, cudaFuncAttributeMaxDynamicSharedMemorySize, OFF_SMEM);
    cudaFuncSetAttribute(samplegemm4_kernel, cudaFuncAttributeMaxDynamicSharedMemorySize, SG_SMEM);

    prep_wtsplit_kernel<<<(KK*C*C+255)/256, 256>>>(cw[0], cw[1]);
    prep_eff_kernel<<<(KK*C*32+255)/256, 256>>>(cw[0], ow[0], mw[0], cb[0], 0);
    prep_eff_kernel<<<(KK*C*32+255)/256, 256>>>(cw[1], ow[1], mw[1], cb[1], 1);

    const int ncos[5] = {20,80,150,210,308};
    const int coff[5] = {0,20,100,250,460};
    for (int i=0;i<5;i++){
        const float* cur = x[i];
        // deform block 1
        offcv2_kernel<<<128,256,OFF_SMEM>>>(cur, 0);
        zerosum_kernel<<<1,128>>>();
        samplegemm4_kernel<<<128,256,SG_SMEM>>>(cur, cb[0], 0);
        normrelu_kernel<<<HW*C/256,256>>>(bg[0], bb[0], pA);
        // deform block 2
        offcv2_kernel<<<128,256,OFF_SMEM>>>(pA, 1);
        zerosum_kernel<<<1,128>>>();
        samplegemm4_kernel<<<128,256,SG_SMEM>>>(pA, cb[1], 1);
        normrelu_kernel<<<HW*C/256,256>>>(bg[1], bb[1], pB);
        // projection(s)
        dim3 g(HW/128, (ncos[i]+127)/128);
        proj2_kernel<<<g, 256>>>(pB, pwa[i], (i>=2) ? cur : nullptr, pwb[i],
                                 outp + (size_t)coff[i]*HW, ncos[i]);
    }
    ln_kernel<<<768*Hh, 128>>>(outp, lnw, lnb);
}

// round 6
// speedup vs baseline: 2.5689x; 1.5025x over previous
#include <cuda_runtime.h>
#include <cuda_bf16.h>
#include <cstdint>

#define Hh 128
#define Ww 128
#define HW 16384
#define C 128
#define KK 9
#define EPS 1e-5f

// ---------------- scratch (device globals; no runtime alloc) ----------------
__device__ float g_bufA[HW*C];
__device__ float g_bufB[HW*C];
__device__ float g_pre[HW*C];
__device__ float g_offs[HW*18];
__device__ float g_maskb[HW*9];
__device__ uint32_t g_wtPh[2][KK*4*128*16];   // [b][k][cc][co][ci-pair] bf16x2 hi
__device__ uint32_t g_wtPl[2][KK*4*128*16];   // lo
__device__ uint32_t g_effPh[2][KK*4*32*16];   // [b][k][cc][j][ci-pair] hi
__device__ uint32_t g_effPl[2][KK*4*32*16];   // lo
__device__ float g_effb[2][32];
__device__ float g_sum[C];
__device__ float g_sumsq[C];

// ---------------- helpers ----------------
__device__ __forceinline__ void bsplit2(float2 v, uint32_t &hp, uint32_t &lp_){
    __nv_bfloat162 h2 = __float22bfloat162_rn(v);
    float2 hf = __bfloat1622float2(h2);
    __nv_bfloat162 l2 = __float22bfloat162_rn(make_float2(v.x - hf.x, v.y - hf.y));
    hp = *reinterpret_cast<uint32_t*>(&h2);
    lp_ = *reinterpret_cast<uint32_t*>(&l2);
}
__device__ __forceinline__ void mma_bf16(float* d, uint32_t a0,uint32_t a1,uint32_t a2,uint32_t a3,
                                         uint32_t b0, uint32_t b1){
    asm volatile("mma.sync.aligned.m16n8k16.row.col.f32.bf16.bf16.f32 "
        "{%0,%1,%2,%3}, {%4,%5,%6,%7}, {%8,%9}, {%0,%1,%2,%3};"
        : "+f"(d[0]),"+f"(d[1]),"+f"(d[2]),"+f"(d[3])
        : "r"(a0),"r"(a1),"r"(a2),"r"(a3),"r"(b0),"r"(b1));
}

// ---------------- prep: pack conv weights as bf16 hi/lo pairs ----------------
// layout: [k][cc][co][16 pairs]  (B operand [co][ci], pairs along ci)
__global__ void prep_wtP_kernel(const float* __restrict__ cw0, const float* __restrict__ cw1){
    int idx = blockIdx.x*blockDim.x + threadIdx.x;
    if (idx >= KK*4*128*16) return;
    int pr = idx & 15, co = (idx>>4)&127, cc = (idx>>11)&3, k = idx>>13;
    int ci0 = cc*32 + pr*2;
    float a0 = cw0[(co*C+ci0)*KK + k], a1 = cw0[(co*C+ci0+1)*KK + k];
    float b0 = cw1[(co*C+ci0)*KK + k], b1 = cw1[(co*C+ci0+1)*KK + k];
    uint32_t hp, lp;
    bsplit2(make_float2(a0,a1), hp, lp);
    g_wtPh[0][idx]=hp; g_wtPl[0][idx]=lp;
    bsplit2(make_float2(b0,b1), hp, lp);
    g_wtPh[1][idx]=hp; g_wtPl[1][idx]=lp;
}

// ---------------- prep: fold ow/mw through cw, pack bf16 hi/lo ----------------
// layout: [k][cc][j<32][16 pairs]
__global__ void prep_effP_kernel(const float* __restrict__ cw, const float* __restrict__ ow,
                                 const float* __restrict__ mw, const float* __restrict__ cb, int b){
    int idx = blockIdx.x*blockDim.x + threadIdx.x;
    if (idx >= KK*4*32*16) return;
    int pr = idx&15, j = (idx>>4)&31, cc=(idx>>9)&3, k=idx>>11;
    int ci0 = cc*32 + pr*2;
    float s0=0.f, s1=0.f;
    if (j < 27){
        const float* P = (j<18) ? (ow + j*C) : (mw + (j-18)*C);
        for (int co=0; co<C; co++){
            float p = P[co];
            s0 += p*cw[(co*C+ci0)*KK + k];
            s1 += p*cw[(co*C+ci0+1)*KK + k];
        }
    }
    uint32_t hp, lp;
    bsplit2(make_float2(s0,s1), hp, lp);
    g_effPh[b][idx]=hp; g_effPl[b][idx]=lp;
    if (idx < 32){
        float bbv = 0.f;
        if (idx < 27){
            const float* P = (idx<18) ? (ow + idx*C) : (mw + (idx-18)*C);
            for (int co=0; co<C; co++) bbv += P[co]*cb[co];
        }
        g_effb[b][idx] = bbv;
    }
}

// ---------------- offsets conv via HMMA: 128px x 27 = x-rows @ effw ----------------
// grid 128, 256 threads (8 warps; warp = 16px). bf16 3-pass.
// smem u32: RH[3*130*18]=7020 | RL=7020 | BOH[9*32*20]=5760 | BOL=5760 -> 25560 u32
#define OC_SMEM (25560*4)
__global__ __launch_bounds__(256) void offcv3_kernel(const float* __restrict__ x, int b){
    extern __shared__ uint32_t su[];
    uint32_t* RH = su;
    uint32_t* RL = su + 7020;
    uint32_t* BOH = su + 14040;
    uint32_t* BOL = su + 19800;
    const int tid = threadIdx.x;
    const int h0 = blockIdx.x, pb = h0*128;
    const int wid = tid>>5, lane = tid&31, lg = lane>>2, lc = lane&3;
    float d[4][4];
#pragma unroll
    for (int nt=0;nt<4;nt++)
#pragma unroll
        for (int i=0;i<4;i++) d[nt][i]=0.f;

    for (int cc=0; cc<4; cc++){
        __syncthreads();
        // build R: rows h0-1,h0,h0+1 chunk cc, padded rows 0/129 zero
#pragma unroll
        for (int t=0;t<2;t++){
            int idx = tid + t*256;
            if (idx < 384){
                int r = idx>>7, px = idx&127;
                int hh = h0 + r - 1;
                uint32_t base = (uint32_t)(r*130 + px + 1)*18;
                if (hh>=0 && hh<Hh){
                    const float4* src = (const float4*)(x + (((hh<<7)+px)<<7) + cc*32);
#pragma unroll
                    for (int i=0;i<8;i++){
                        float4 v = src[i];
                        uint32_t h0p,l0p,h1p,l1p;
                        bsplit2(make_float2(v.x,v.y), h0p,l0p);
                        bsplit2(make_float2(v.z,v.w), h1p,l1p);
                        *(uint2*)(RH + base + i*2) = make_uint2(h0p,h1p);
                        *(uint2*)(RL + base + i*2) = make_uint2(l0p,l1p);
                    }
                } else {
#pragma unroll
                    for (int i=0;i<8;i++){
                        *(uint2*)(RH + base + i*2) = make_uint2(0u,0u);
                        *(uint2*)(RL + base + i*2) = make_uint2(0u,0u);
                    }
                }
            }
        }
        if (tid < 96){
            int slot = tid>>4, pr = tid&15;
            int r = slot>>1, side = slot&1;
            uint32_t base = (uint32_t)(r*130 + (side?129:0))*18;
            RH[base+pr]=0u; RL[base+pr]=0u;
        }
        // load B: all 9 taps for chunk cc
#pragma unroll
        for (int t=0;t<18;t++){
            int idx = tid + t*256;     // < 4608
            int k = idx>>9, rr = idx & 511;
            int j = rr>>4, pr = rr&15;
            uint32_t gidx = (uint32_t)((k*4+cc)<<9) + (uint32_t)rr;
            BOH[(uint32_t)(k*32+j)*20 + pr] = g_effPh[b][gidx];
            BOL[(uint32_t)(k*32+j)*20 + pr] = g_effPl[b][gidx];
        }
        __syncthreads();
        // mma over taps
        for (int k=0;k<KK;k++){
            int ky = k/3, kx = k - ky*3 - 1;
#pragma unroll
            for (int ks=0; ks<2; ks++){
                uint32_t row = (uint32_t)(wid*16 + lg + kx + 1);
                uint32_t abase = ((uint32_t)ky*130 + row)*18 + ks*8 + lc;
                uint32_t ah0 = RH[abase],      ah1 = RH[abase + 144];
                uint32_t ah2 = RH[abase + 4],  ah3 = RH[abase + 148];
                uint32_t al0 = RL[abase],      al1 = RL[abase + 144];
                uint32_t al2 = RL[abase + 4],  al3 = RL[abase + 148];
#pragma unroll
                for (int nt=0;nt<4;nt++){
                    uint32_t bb = (uint32_t)(k*32 + nt*8 + lg)*20 + ks*8 + lc;
                    uint32_t b0 = BOH[bb], b1 = BOH[bb+4];
                    mma_bf16(d[nt], ah0,ah1,ah2,ah3, b0,b1);
                }
#pragma unroll
                for (int nt=0;nt<4;nt++){
                    uint32_t bb = (uint32_t)(k*32 + nt*8 + lg)*20 + ks*8 + lc;
                    uint32_t b0 = BOL[bb], b1 = BOL[bb+4];
                    mma_bf16(d[nt], ah0,ah1,ah2,ah3, b0,b1);
                }
#pragma unroll
                for (int nt=0;nt<4;nt++){
                    uint32_t bb = (uint32_t)(k*32 + nt*8 + lg)*20 + ks*8 + lc;
                    uint32_t b0 = BOH[bb], b1 = BOH[bb+4];
                    mma_bf16(d[nt], al0,al1,al2,al3, b0,b1);
                }
            }
        }
    }
    // epilogue: logits -> Vs -> offsets + softmax
    __syncthreads();
    float* Vs = (float*)su;  // [128][33]
#pragma unroll
    for (int nt=0;nt<4;nt++){
        int col = nt*8 + lc*2;
        int r0 = wid*16 + lg;
        Vs[r0*33 + col]       = d[nt][0] + g_effb[b][col];
        Vs[r0*33 + col + 1]   = d[nt][1] + g_effb[b][col+1];
        Vs[(r0+8)*33 + col]   = d[nt][2] + g_effb[b][col];
        Vs[(r0+8)*33 + col+1] = d[nt][3] + g_effb[b][col+1];
    }
    __syncthreads();
    if (tid < 128){
        int p = pb + tid;
        const float* v = Vs + tid*33;
#pragma unroll
        for (int j=0;j<18;j++) g_offs[p*18+j] = v[j];
        float mx = v[18];
#pragma unroll
        for (int j=19;j<27;j++) mx = fmaxf(mx, v[j]);
        float e[9]; float smv = 0.f;
#pragma unroll
        for (int j=0;j<9;j++){ e[j] = expf(v[18+j]-mx); smv += e[j]; }
        float inv = 1.f/smv;
#pragma unroll
        for (int j=0;j<9;j++) g_maskb[p*9+j] = e[j]*inv;
    }
}

// ---------------- warp-specialized bf16-split sample-GEMM ----------------
// grid 128, 512 threads: warps 0-7 = MMA consumers, warps 8-15 = producers.
// smem u32 layout:
//  AH[2]: 0, 2304   AL[2]: 4608, 6912    (128*18 each)
//  BH[2]: 9216, 11776   BL[2]: 14336, 16896  (128*20 each)
//  Ps: 19456 (512 f)  Ps2: 19968 (512 f) ; total 20480 u32
#define SG5_SMEM (20480*4)

struct SampStage {
    float4 sA[4][4];     // [corner][i]
    uint4  sB[4];        // bh0,bh1,bl0,bl1
    float w00,w01,w10,w11,mk;
};

__device__ __forceinline__ void stage_load(SampStage& st, const float* __restrict__ x, int b,
                                           int h0, int pb, int lp, int q, int bt, int it){
    int k = it>>2, cc = it&3;
    int p = pb + lp;
    float offy = g_offs[p*18 + 2*k];
    float offx = g_offs[p*18 + 2*k + 1];
    st.mk = g_maskb[p*9 + k];
    float py = (float)(h0 - 1 + k/3) + offy;
    float pxf = (float)(lp - 1 + (k - (k/3)*3)) + offx;
    float y0f = floorf(py), x0f = floorf(pxf);
    int y0 = (int)y0f, x0i = (int)x0f;
    float wy1 = py - y0f, wy0 = 1.f - wy1;
    float wx1 = pxf - x0f, wx0 = 1.f - wx1;
    int y1 = y0+1, x1i = x0i+1;
    bool vy0 = (y0>=0)&(y0<Hh), vy1 = (y1>=0)&(y1<Hh);
    bool vx0 = (x0i>=0)&(x0i<Ww), vx1 = (x1i>=0)&(x1i<Ww);
    st.w00 = (vy0&&vx0)? wy0*wx0 : 0.f;
    st.w01 = (vy0&&vx1)? wy0*wx1 : 0.f;
    st.w10 = (vy1&&vx0)? wy1*wx0 : 0.f;
    st.w11 = (vy1&&vx1)? wy1*wx1 : 0.f;
    int y0c = min(max(y0,0),Hh-1), y1c = min(max(y1,0),Hh-1);
    int x0c = min(max(x0i,0),Ww-1), x1c = min(max(x1i,0),Ww-1);
    int cg = cc*32 + q*16;
    const float4* r00 = (const float4*)(x + (((y0c<<7)+x0c)<<7) + cg);
    const float4* r01 = (const float4*)(x + (((y0c<<7)+x1c)<<7) + cg);
    const float4* r10 = (const float4*)(x + (((y1c<<7)+x0c)<<7) + cg);
    const float4* r11 = (const float4*)(x + (((y1c<<7)+x1c)<<7) + cg);
#pragma unroll
    for (int i=0;i<4;i++){
        st.sA[0][i] = r00[i];
        st.sA[1][i] = r01[i];
        st.sA[2][i] = r10[i];
        st.sA[3][i] = r11[i];
    }
    uint32_t cbase = (uint32_t)((k*4+cc)*2048) + (uint32_t)bt*8;
    st.sB[0] = *(const uint4*)(&g_wtPh[b][cbase]);
    st.sB[1] = *(const uint4*)(&g_wtPh[b][cbase+4]);
    st.sB[2] = *(const uint4*)(&g_wtPl[b][cbase]);
    st.sB[3] = *(const uint4*)(&g_wtPl[b][cbase+4]);
}

__device__ __forceinline__ void stage_store(SampStage& st, uint32_t* AH, uint32_t* AL,
                                            uint32_t* BH, uint32_t* BL, int lp, int q, int bt){
    uint32_t abase = (uint32_t)lp*18 + q*8;
#pragma unroll
    for (int i=0;i<4;i++){
        float4 a = st.sA[0][i], b4 = st.sA[1][i], c4 = st.sA[2][i], e4 = st.sA[3][i];
        float4 o;
        o.x = st.mk*(st.w00*a.x + st.w01*b4.x + st.w10*c4.x + st.w11*e4.x);
        o.y = st.mk*(st.w00*a.y + st.w01*b4.y + st.w10*c4.y + st.w11*e4.y);
        o.z = st.mk*(st.w00*a.z + st.w01*b4.z + st.w10*c4.z + st.w11*e4.z);
        o.w = st.mk*(st.w00*a.w + st.w01*b4.w + st.w10*c4.w + st.w11*e4.w);
        uint32_t h0p,l0p,h1p,l1p;
        bsplit2(make_float2(o.x,o.y), h0p,l0p);
        bsplit2(make_float2(o.z,o.w), h1p,l1p);
        *(uint2*)(AH + abase + i*2) = make_uint2(h0p,h1p);
        *(uint2*)(AL + abase + i*2) = make_uint2(l0p,l1p);
    }
    uint32_t bbase = (uint32_t)(bt>>1)*20 + (bt&1)*8;
    *(uint4*)(BH + bbase)     = st.sB[0];
    *(uint4*)(BH + bbase + 4) = st.sB[1];
    *(uint4*)(BL + bbase)     = st.sB[2];
    *(uint4*)(BL + bbase + 4) = st.sB[3];
}

__device__ __forceinline__ void mma_chunk(float d[2][8][4], const uint32_t* AH, const uint32_t* AL,
                                          const uint32_t* BH, const uint32_t* BL,
                                          int warpM, int warpN, int lg, int lc){
#pragma unroll
    for (int ks=0; ks<2; ks++){
        uint32_t ah[2][4], al[2][4];
#pragma unroll
        for (int mt=0;mt<2;mt++){
            uint32_t base = (uint32_t)(warpM*32 + mt*16 + lg)*18 + ks*8 + lc;
            ah[mt][0]=AH[base]; ah[mt][1]=AH[base+144]; ah[mt][2]=AH[base+4]; ah[mt][3]=AH[base+148];
            al[mt][0]=AL[base]; al[mt][1]=AL[base+144]; al[mt][2]=AL[base+4]; al[mt][3]=AL[base+148];
        }
#pragma unroll
        for (int nt=0;nt<8;nt++){
            uint32_t bb = (uint32_t)(warpN*64 + nt*8 + lg)*20 + ks*8 + lc;
            uint32_t b0 = BH[bb], b1 = BH[bb+4];
            mma_bf16(d[0][nt], ah[0][0],ah[0][1],ah[0][2],ah[0][3], b0,b1);
            mma_bf16(d[1][nt], ah[1][0],ah[1][1],ah[1][2],ah[1][3], b0,b1);
        }
#pragma unroll
        for (int nt=0;nt<8;nt++){
            uint32_t bb = (uint32_t)(warpN*64 + nt*8 + lg)*20 + ks*8 + lc;
            uint32_t b0 = BL[bb], b1 = BL[bb+4];
            mma_bf16(d[0][nt], ah[0][0],ah[0][1],ah[0][2],ah[0][3], b0,b1);
            mma_bf16(d[1][nt], ah[1][0],ah[1][1],ah[1][2],ah[1][3], b0,b1);
        }
#pragma unroll
        for (int nt=0;nt<8;nt++){
            uint32_t bb = (uint32_t)(warpN*64 + nt*8 + lg)*20 + ks*8 + lc;
            uint32_t b0 = BH[bb], b1 = BH[bb+4];
            mma_bf16(d[0][nt], al[0][0],al[0][1],al[0][2],al[0][3], b0,b1);
            mma_bf16(d[1][nt], al[1][0],al[1][1],al[1][2],al[1][3], b0,b1);
        }
    }
}

__global__ __launch_bounds__(512) void samplegemm5_kernel(const float* __restrict__ x,
                                                          const float* __restrict__ cb, int b){
    extern __shared__ uint32_t su[];
    uint32_t* AHb[2] = {su,        su + 2304};
    uint32_t* ALb[2] = {su + 4608, su + 6912};
    uint32_t* BHb[2] = {su + 9216, su + 11776};
    uint32_t* BLb[2] = {su + 14336, su + 16896};
    float* Ps  = (float*)(su + 19456);
    float* Ps2 = (float*)(su + 19968);
    const int tid = threadIdx.x;
    const int h0 = blockIdx.x, pb = h0*128;
    const bool producer = (tid >= 256);
    const int bt = tid - 256;               // producer index
    const int lp = bt>>1, q = bt&1;
    const int wid = tid>>5, lane = tid&31, lg = lane>>2, lc = lane&3;
    const int warpM = wid&3, warpN = (wid>>2)&1;

    float d[2][8][4];
#pragma unroll
    for (int mt=0;mt<2;mt++)
#pragma unroll
        for (int nt=0;nt<8;nt++)
#pragma unroll
            for (int i=0;i<4;i++) d[mt][nt][i]=0.f;

    SampStage st;
    if (producer){
        stage_load(st, x, b, h0, pb, lp, q, bt, 0);
        stage_store(st, AHb[0], ALb[0], BHb[0], BLb[0], lp, q, bt);
    }
    __syncthreads();
    for (int it=0; it<36; it++){
        if (!producer){
            int bf = it & 1;
            mma_chunk(d, AHb[bf], ALb[bf], BHb[bf], BLb[bf], warpM, warpN, lg, lc);
        } else if (it < 35){
            int nb = (it+1)&1;
            stage_load(st, x, b, h0, pb, lp, q, bt, it+1);
            stage_store(st, AHb[nb], ALb[nb], BHb[nb], BLb[nb], lp, q, bt);
        }
        __syncthreads();
    }

    // ---------------- epilogue ----------------
    float* Vs = (float*)su;   // [128][132]
    if (!producer){
#pragma unroll
        for (int mt=0;mt<2;mt++){
            int r0 = warpM*32 + mt*16 + lg;
#pragma unroll
            for (int nt=0;nt<8;nt++){
                int co0 = warpN*64 + nt*8 + lc*2;
                float b0v = cb[co0], b1v = cb[co0+1];
                *(float2*)(Vs + r0*132 + co0)     = make_float2(d[mt][nt][0]+b0v, d[mt][nt][1]+b1v);
                *(float2*)(Vs + (r0+8)*132 + co0) = make_float2(d[mt][nt][2]+b0v, d[mt][nt][3]+b1v);
            }
        }
    }
    __syncthreads();
    // coalesced store to g_pre
#pragma unroll
    for (int t=0;t<32;t++){
        int idx = tid + t*512;
        int px = idx >> 7, co = idx & 127;
        g_pre[(pb+px)*C + co] = Vs[px*132 + co];
    }
    // fused per-channel stats
    {
        int co = tid & 127, qq = tid >> 7;  // qq 0..3
        float S = 0.f, Q = 0.f;
#pragma unroll 8
        for (int i=0;i<32;i++){
            float v = Vs[(qq*32+i)*132 + co];
            S += v; Q += v*v;
        }
        Ps[qq*128 + co] = S;
        Ps2[qq*128 + co] = Q;
        __syncthreads();
        if (tid < 128){
            float SS = Ps[tid] + Ps[128+tid] + Ps[256+tid] + Ps[384+tid];
            float QQ = Ps2[tid] + Ps2[128+tid] + Ps2[256+tid] + Ps2[384+tid];
            atomicAdd(&g_sum[tid], SS);
            atomicAdd(&g_sumsq[tid], QQ);
        }
    }
}

// ---------------- instance-norm helpers ----------------
__global__ void zerosum_kernel(){
    int t = threadIdx.x;
    if (t < C){ g_sum[t]=0.f; g_sumsq[t]=0.f; }
}

__global__ void normrelu_kernel(const float* __restrict__ bg, const float* __restrict__ bb,
                                float* __restrict__ out){
    int idx = blockIdx.x*blockDim.x + threadIdx.x;
    int c = idx & 127;
    float mu = g_sum[c] * (1.f/HW);
    float var = g_sumsq[c] * (1.f/HW) - mu*mu;
    float v = (g_pre[idx]-mu)*rsqrtf(var+EPS)*bg[c] + bb[c];
    out[idx] = fmaxf(v, 0.f);
}

// ---------------- projections (SIMT fp32) ----------------
__global__ __launch_bounds__(256) void proj2_kernel(const float* __restrict__ xa, const float* __restrict__ wa,
        const float* __restrict__ xb, const float* __restrict__ wb, float* __restrict__ out, int nco){
    __shared__ float As[128*36];
    __shared__ float Bs[32*128];
    const int tid = threadIdx.x;
    const int pb = blockIdx.x*128;
    const int cbase = blockIdx.y*128;
    const int pid = tid >> 4, cid = tid & 15;
    float acc[8][8];
#pragma unroll
    for (int i=0;i<8;i++)
#pragma unroll
        for (int j=0;j<8;j++) acc[i][j]=0.f;

    int nsrc = (xb != nullptr) ? 2 : 1;
    for (int s=0; s<nsrc; s++){
        const float* xs = s ? xb : xa;
        const float* ws = s ? wb : wa;
        for (int cc=0; cc<4; cc++){
            __syncthreads();
#pragma unroll
            for (int t=0;t<16;t++){
                int idx = tid + t*256;
                int px = idx >> 5, ci = idx & 31;
                As[px*36 + ci] = xs[(pb+px)*C + cc*32 + ci];
            }
#pragma unroll
            for (int t=0;t<16;t++){
                int idx = tid + t*256;
                int ci = idx >> 7, co = idx & 127;
                int cog = cbase + co;
                Bs[ci*128 + co] = (cog < nco) ? ws[cog*C + cc*32 + ci] : 0.f;
            }
            __syncthreads();
#pragma unroll
            for (int ci4=0; ci4<8; ci4++){
                float4 a[8];
#pragma unroll
                for (int i=0;i<8;i++) a[i] = *(const float4*)(As + (pid*8+i)*36 + ci4*4);
                const float* ap = (const float*)a;
#pragma unroll
                for (int u=0;u<4;u++){
                    float4 b0 = *(const float4*)(Bs + (ci4*4+u)*128 + cid*8);
                    float4 b1 = *(const float4*)(Bs + (ci4*4+u)*128 + cid*8 + 4);
                    float bvv[8] = {b0.x,b0.y,b0.z,b0.w,b1.x,b1.y,b1.z,b1.w};
#pragma unroll
                    for (int i=0;i<8;i++)
#pragma unroll
                        for (int j=0;j<8;j++) acc[i][j] += ap[i*4+u]*bvv[j];
                }
            }
        }
    }
#pragma unroll
    for (int j=0;j<8;j++){
        int co = cbase + cid*8 + j;
        if (co < nco){
            float4 o0 = make_float4(acc[0][j],acc[1][j],acc[2][j],acc[3][j]);
            float4 o1 = make_float4(acc[4][j],acc[5][j],acc[6][j],acc[7][j]);
            float* dst = out + (size_t)co*HW + pb + pid*8;
            *(float4*)dst = o0;
            *(float4*)(dst+4) = o1;
        }
    }
}

// ---------------- final layernorm over W ----------------
__global__ __launch_bounds__(128) void ln_kernel(float* __restrict__ o, const float* __restrict__ lnw,
                                                 const float* __restrict__ lnb){
    __shared__ float ss[4], ssq[4];
    int row = blockIdx.x;
    float* r = o + (size_t)row*128;
    int t = threadIdx.x;
    float v = r[t];
    float s = v, sq = v*v;
#pragma unroll
    for (int off=16; off; off>>=1){
        s  += __shfl_down_sync(0xffffffffu, s, off);
        sq += __shfl_down_sync(0xffffffffu, sq, off);
    }
    int wid = t >> 5, lane = t & 31;
    if (lane==0){ ss[wid]=s; ssq[wid]=sq; }
    __syncthreads();
    float S  = ss[0]+ss[1]+ss[2]+ss[3];
    float SQ = ssq[0]+ssq[1]+ssq[2]+ssq[3];
    float mu = S*(1.f/128.f);
    float var = SQ*(1.f/128.f) - mu*mu;
    r[t] = (v-mu)*rsqrtf(var+EPS)*lnw[t] + lnb[t];
}

// ---------------- host orchestration ----------------
extern "C" void kernel_launch(void* const* d_in, const int* in_sizes, int n_in,
                              void* d_out, int out_size){
    (void)in_sizes; (void)n_in; (void)out_size;
    const float* x[5];
    for (int i=0;i<5;i++) x[i] = (const float*)d_in[i];
    const float* cw[2] = {(const float*)d_in[5],  (const float*)d_in[11]};
    const float* cb[2] = {(const float*)d_in[6],  (const float*)d_in[12]};
    const float* ow[2] = {(const float*)d_in[7],  (const float*)d_in[13]};
    const float* mw[2] = {(const float*)d_in[8],  (const float*)d_in[14]};
    const float* bg[2] = {(const float*)d_in[9],  (const float*)d_in[15]};
    const float* bb[2] = {(const float*)d_in[10], (const float*)d_in[16]};
    const float* pwa[5] = {(const float*)d_in[17], (const float*)d_in[18], (const float*)d_in[19],
                           (const float*)d_in[21], (const float*)d_in[23]};
    const float* pwb[5] = {nullptr, nullptr, (const float*)d_in[20],
                           (const float*)d_in[22], (const float*)d_in[24]};
    const float* lnw = (const float*)d_in[25];
    const float* lnb = (const float*)d_in[26];
    float* outp = (float*)d_out;

    float *pA=nullptr, *pB=nullptr;
    cudaGetSymbolAddress((void**)&pA, g_bufA);
    cudaGetSymbolAddress((void**)&pB, g_bufB);

    cudaFuncSetAttribute(offcv3_kernel, cudaFuncAttributeMaxDynamicSharedMemorySize, OC_SMEM);
    cudaFuncSetAttribute(samplegemm5_kernel, cudaFuncAttributeMaxDynamicSharedMemorySize, SG5_SMEM);

    prep_wtP_kernel<<<(KK*4*128*16+255)/256, 256>>>(cw[0], cw[1]);
    prep_effP_kernel<<<(KK*4*32*16+255)/256, 256>>>(cw[0], ow[0], mw[0], cb[0], 0);
    prep_effP_kernel<<<(KK*4*32*16+255)/256, 256>>>(cw[1], ow[1], mw[1], cb[1], 1);

    const int ncos[5] = {20,80,150,210,308};
    const int coff[5] = {0,20,100,250,460};
    for (int i=0;i<5;i++){
        const float* cur = x[i];
        // deform block 1
        offcv3_kernel<<<128,256,OC_SMEM>>>(cur, 0);
        zerosum_kernel<<<1,128>>>();
        samplegemm5_kernel<<<128,512,SG5_SMEM>>>(cur, cb[0], 0);
        normrelu_kernel<<<HW*C/256,256>>>(bg[0], bb[0], pA);
        // deform block 2
        offcv3_kernel<<<128,256,OC_SMEM>>>(pA, 1);
        zerosum_kernel<<<1,128>>>();
        samplegemm5_kernel<<<128,512,SG5_SMEM>>>(pA, cb[1], 1);
        normrelu_kernel<<<HW*C/256,256>>>(bg[1], bb[1], pB);
        // projection(s)
        dim3 g(HW/128, (ncos[i]+127)/128);
        proj2_kernel<<<g, 256>>>(pB, pwa[i], (i>=2) ? cur : nullptr, pwb[i],
                                 outp + (size_t)coff[i]*HW, ncos[i]);
    }
    ln_kernel<<<768*Hh, 128>>>(outp, lnw, lnb);
}

// round 7
// speedup vs baseline: 2.6868x; 1.0459x over previous
#include <cuda_runtime.h>
#include <cuda_bf16.h>
#include <cstdint>

#define Hh 128
#define Ww 128
#define HW 16384
#define C 128
#define KK 9
#define EPS 1e-5f
#define NIMG 5

struct Ptr5 { const float* p[NIMG]; };

// ---------------- scratch (device globals; no runtime alloc) ----------------
__device__ float g_bufA[NIMG*HW*C];
__device__ float g_bufB[NIMG*HW*C];
__device__ float g_pre[NIMG*HW*C];
__device__ float g_offs[NIMG*HW*18];
__device__ float g_maskb[NIMG*HW*9];
__device__ uint32_t g_wtPh[2][KK*4*128*16];   // [b][k][cc][co][pair] bf16x2 hi
__device__ uint32_t g_wtPl[2][KK*4*128*16];
__device__ uint32_t g_effPh[2][KK*4*32*16];
__device__ uint32_t g_effPl[2][KK*4*32*16];
__device__ float g_effb[2][32];
__device__ uint32_t g_pjH[1280*128];          // proj weights [row][128 pairs] (K=256)
__device__ uint32_t g_pjL[1280*128];
__device__ float g_sumA[2*NIMG*128];
__device__ float g_sqA[2*NIMG*128];

__constant__ int c_ncos[5]   = {20,80,150,210,308};
__constant__ int c_pjbase[5] = {0,128,256,512,896};
__constant__ int c_coff[5]   = {0,20,100,250,460};

// ---------------- helpers ----------------
__device__ __forceinline__ void bsplit2(float2 v, uint32_t &hp, uint32_t &lp_){
    __nv_bfloat162 h2 = __float22bfloat162_rn(v);
    float2 hf = __bfloat1622float2(h2);
    __nv_bfloat162 l2 = __float22bfloat162_rn(make_float2(v.x - hf.x, v.y - hf.y));
    hp = *reinterpret_cast<uint32_t*>(&h2);
    lp_ = *reinterpret_cast<uint32_t*>(&l2);
}
__device__ __forceinline__ void mma_bf16(float* d, uint32_t a0,uint32_t a1,uint32_t a2,uint32_t a3,
                                         uint32_t b0, uint32_t b1){
    asm volatile("mma.sync.aligned.m16n8k16.row.col.f32.bf16.bf16.f32 "
        "{%0,%1,%2,%3}, {%4,%5,%6,%7}, {%8,%9}, {%0,%1,%2,%3};"
        : "+f"(d[0]),"+f"(d[1]),"+f"(d[2]),"+f"(d[3])
        : "r"(a0),"r"(a1),"r"(a2),"r"(a3),"r"(b0),"r"(b1));
}

// 3-pass bf16-split MMA over one K=32 chunk; A/B smem stride 20 u32 per row.
__device__ __forceinline__ void mma_chunk3(float d[2][4][4],
    const uint32_t* __restrict__ AH, const uint32_t* __restrict__ AL,
    const uint32_t* __restrict__ BH, const uint32_t* __restrict__ BL,
    int warpM, int warpN, int lg, int lc){
#pragma unroll
    for (int ks=0; ks<2; ks++){
        uint32_t ah[2][4], al[2][4];
#pragma unroll
        for (int mt=0;mt<2;mt++){
            uint32_t base = (uint32_t)(warpM*32+mt*16+lg)*20 + ks*8 + lc;
            ah[mt][0]=AH[base]; ah[mt][1]=AH[base+160]; ah[mt][2]=AH[base+4]; ah[mt][3]=AH[base+164];
            al[mt][0]=AL[base]; al[mt][1]=AL[base+160]; al[mt][2]=AL[base+4]; al[mt][3]=AL[base+164];
        }
        uint32_t bh[4][2];
#pragma unroll
        for (int nt=0;nt<4;nt++){
            uint32_t bb = (uint32_t)(warpN*32+nt*8+lg)*20 + ks*8 + lc;
            bh[nt][0]=BH[bb]; bh[nt][1]=BH[bb+4];
            mma_bf16(d[0][nt], ah[0][0],ah[0][1],ah[0][2],ah[0][3], bh[nt][0],bh[nt][1]);
            mma_bf16(d[1][nt], ah[1][0],ah[1][1],ah[1][2],ah[1][3], bh[nt][0],bh[nt][1]);
        }
#pragma unroll
        for (int nt=0;nt<4;nt++){
            uint32_t bb = (uint32_t)(warpN*32+nt*8+lg)*20 + ks*8 + lc;
            uint32_t b0=BL[bb], b1=BL[bb+4];
            mma_bf16(d[0][nt], ah[0][0],ah[0][1],ah[0][2],ah[0][3], b0,b1);
            mma_bf16(d[1][nt], ah[1][0],ah[1][1],ah[1][2],ah[1][3], b0,b1);
        }
#pragma unroll
        for (int nt=0;nt<4;nt++){
            mma_bf16(d[0][nt], al[0][0],al[0][1],al[0][2],al[0][3], bh[nt][0],bh[nt][1]);
            mma_bf16(d[1][nt], al[1][0],al[1][1],al[1][2],al[1][3], bh[nt][0],bh[nt][1]);
        }
    }
}

// ---------------- prep kernels ----------------
__global__ void prep_wtP_kernel(const float* __restrict__ cw0, const float* __restrict__ cw1){
    int idx = blockIdx.x*blockDim.x + threadIdx.x;
    if (idx >= KK*4*128*16) return;
    int pr = idx & 15, co = (idx>>4)&127, cc = (idx>>11)&3, k = idx>>13;
    int ci0 = cc*32 + pr*2;
    uint32_t hp, lp;
    bsplit2(make_float2(cw0[(co*C+ci0)*KK + k], cw0[(co*C+ci0+1)*KK + k]), hp, lp);
    g_wtPh[0][idx]=hp; g_wtPl[0][idx]=lp;
    bsplit2(make_float2(cw1[(co*C+ci0)*KK + k], cw1[(co*C+ci0+1)*KK + k]), hp, lp);
    g_wtPh[1][idx]=hp; g_wtPl[1][idx]=lp;
}

__global__ void prep_effP_kernel(const float* __restrict__ cw, const float* __restrict__ ow,
                                 const float* __restrict__ mw, const float* __restrict__ cb, int b){
    int idx = blockIdx.x*blockDim.x + threadIdx.x;
    if (idx >= KK*4*32*16) return;
    int pr = idx&15, j = (idx>>4)&31, cc=(idx>>9)&3, k=idx>>11;
    int ci0 = cc*32 + pr*2;
    float s0=0.f, s1=0.f;
    if (j < 27){
        const float* P = (j<18) ? (ow + j*C) : (mw + (j-18)*C);
        for (int co=0; co<C; co++){
            float p = P[co];
            s0 += p*cw[(co*C+ci0)*KK + k];
            s1 += p*cw[(co*C+ci0+1)*KK + k];
        }
    }
    uint32_t hp, lp;
    bsplit2(make_float2(s0,s1), hp, lp);
    g_effPh[b][idx]=hp; g_effPl[b][idx]=lp;
    if (idx < 32){
        float bbv = 0.f;
        if (idx < 27){
            const float* P = (idx<18) ? (ow + idx*C) : (mw + (idx-18)*C);
            for (int co=0; co<C; co++) bbv += P[co]*cb[co];
        }
        g_effb[b][idx] = bbv;
    }
}

__global__ void prep_pj_kernel(Ptr5 wa, Ptr5 wb){
    int idx = blockIdx.x*blockDim.x + threadIdx.x;
    if (idx >= 1280*128) return;
    int u = idx & 127, row = idx >> 7;
    int img = 0;
#pragma unroll
    for (int i=1;i<5;i++) if (row >= c_pjbase[i]) img = i;
    int lco = row - c_pjbase[img];
    float v0=0.f, v1=0.f;
    if (lco < c_ncos[img]){
        if (u < 64){
            const float* w = wa.p[img];
            v0 = w[lco*C + u*2]; v1 = w[lco*C + u*2+1];
        } else {
            const float* w = wb.p[img];
            if (w){ v0 = w[lco*C + (u-64)*2]; v1 = w[lco*C + (u-64)*2+1]; }
        }
    }
    uint32_t hp, lp;
    bsplit2(make_float2(v0,v1), hp, lp);
    g_pjH[idx]=hp; g_pjL[idx]=lp;
}

__global__ void zero_sums_kernel(){
    int t = blockIdx.x*blockDim.x + threadIdx.x;
    if (t < 2*NIMG*128){ g_sumA[t]=0.f; g_sqA[t]=0.f; }
}

// ---------------- offsets conv via HMMA (bf16 3-pass) ----------------
#define OC_SMEM (25560*4)
__global__ __launch_bounds__(256) void offcv3_kernel(Ptr5 xs, int b){
    extern __shared__ uint32_t su[];
    uint32_t* RH = su;
    uint32_t* RL = su + 7020;
    uint32_t* BOH = su + 14040;
    uint32_t* BOL = su + 19800;
    const int tid = threadIdx.x;
    const int h0 = blockIdx.x, img = blockIdx.y, pb = h0*128;
    const float* x = xs.p[img];
    float* offs = g_offs + (size_t)img*HW*18;
    float* mkb  = g_maskb + (size_t)img*HW*9;
    const int wid = tid>>5, lane = tid&31, lg = lane>>2, lc = lane&3;
    float d[4][4];
#pragma unroll
    for (int nt=0;nt<4;nt++)
#pragma unroll
        for (int i=0;i<4;i++) d[nt][i]=0.f;

    for (int cc=0; cc<4; cc++){
        __syncthreads();
#pragma unroll
        for (int t=0;t<2;t++){
            int idx = tid + t*256;
            if (idx < 384){
                int r = idx>>7, px = idx&127;
                int hh = h0 + r - 1;
                uint32_t base = (uint32_t)(r*130 + px + 1)*18;
                if (hh>=0 && hh<Hh){
                    const float4* src = (const float4*)(x + (((hh<<7)+px)<<7) + cc*32);
#pragma unroll
                    for (int i=0;i<8;i++){
                        float4 v = src[i];
                        uint32_t h0p,l0p,h1p,l1p;
                        bsplit2(make_float2(v.x,v.y), h0p,l0p);
                        bsplit2(make_float2(v.z,v.w), h1p,l1p);
                        *(uint2*)(RH + base + i*2) = make_uint2(h0p,h1p);
                        *(uint2*)(RL + base + i*2) = make_uint2(l0p,l1p);
                    }
                } else {
#pragma unroll
                    for (int i=0;i<8;i++){
                        *(uint2*)(RH + base + i*2) = make_uint2(0u,0u);
                        *(uint2*)(RL + base + i*2) = make_uint2(0u,0u);
                    }
                }
            }
        }
        if (tid < 96){
            int slot = tid>>4, pr = tid&15;
            int r = slot>>1, side = slot&1;
            uint32_t base = (uint32_t)(r*130 + (side?129:0))*18;
            RH[base+pr]=0u; RL[base+pr]=0u;
        }
#pragma unroll
        for (int t=0;t<18;t++){
            int idx = tid + t*256;
            int k = idx>>9, rr = idx & 511;
            int j = rr>>4, pr = rr&15;
            uint32_t gidx = (uint32_t)((k*4+cc)<<9) + (uint32_t)rr;
            BOH[(uint32_t)(k*32+j)*20 + pr] = g_effPh[b][gidx];
            BOL[(uint32_t)(k*32+j)*20 + pr] = g_effPl[b][gidx];
        }
        __syncthreads();
        for (int k=0;k<KK;k++){
            int ky = k/3, kx = k - ky*3 - 1;
#pragma unroll
            for (int ks=0; ks<2; ks++){
                uint32_t row = (uint32_t)(wid*16 + lg + kx + 1);
                uint32_t abase = ((uint32_t)ky*130 + row)*18 + ks*8 + lc;
                uint32_t ah0 = RH[abase],      ah1 = RH[abase + 144];
                uint32_t ah2 = RH[abase + 4],  ah3 = RH[abase + 148];
                uint32_t al0 = RL[abase],      al1 = RL[abase + 144];
                uint32_t al2 = RL[abase + 4],  al3 = RL[abase + 148];
#pragma unroll
                for (int nt=0;nt<4;nt++){
                    uint32_t bb = (uint32_t)(k*32 + nt*8 + lg)*20 + ks*8 + lc;
                    uint32_t b0 = BOH[bb], b1 = BOH[bb+4];
                    mma_bf16(d[nt], ah0,ah1,ah2,ah3, b0,b1);
                }
#pragma unroll
                for (int nt=0;nt<4;nt++){
                    uint32_t bb = (uint32_t)(k*32 + nt*8 + lg)*20 + ks*8 + lc;
                    uint32_t b0 = BOL[bb], b1 = BOL[bb+4];
                    mma_bf16(d[nt], ah0,ah1,ah2,ah3, b0,b1);
                }
#pragma unroll
                for (int nt=0;nt<4;nt++){
                    uint32_t bb = (uint32_t)(k*32 + nt*8 + lg)*20 + ks*8 + lc;
                    uint32_t b0 = BOH[bb], b1 = BOH[bb+4];
                    mma_bf16(d[nt], al0,al1,al2,al3, b0,b1);
                }
            }
        }
    }
    __syncthreads();
    float* Vs = (float*)su;  // [128][33]
#pragma unroll
    for (int nt=0;nt<4;nt++){
        int col = nt*8 + lc*2;
        int r0 = wid*16 + lg;
        Vs[r0*33 + col]       = d[nt][0] + g_effb[b][col];
        Vs[r0*33 + col + 1]   = d[nt][1] + g_effb[b][col+1];
        Vs[(r0+8)*33 + col]   = d[nt][2] + g_effb[b][col];
        Vs[(r0+8)*33 + col+1] = d[nt][3] + g_effb[b][col+1];
    }
    __syncthreads();
    if (tid < 128){
        int p = pb + tid;
        const float* v = Vs + tid*33;
#pragma unroll
        for (int j=0;j<18;j++) offs[p*18+j] = v[j];
        float mx = v[18];
#pragma unroll
        for (int j=19;j<27;j++) mx = fmaxf(mx, v[j]);
        float e[9]; float smv = 0.f;
#pragma unroll
        for (int j=0;j<9;j++){ e[j] = expf(v[18+j]-mx); smv += e[j]; }
        float inv = 1.f/smv;
#pragma unroll
        for (int j=0;j<9;j++) mkb[p*9+j] = e[j]*inv;
    }
}

// ---------------- homogeneous pipelined sample-GEMM ----------------
// grid (128,5), 512 threads, all warps gather + MMA. Warp tile 32px x 32co.
#define SGB 2560
#define SG6_SMEM (8*SGB*4)   // 81920 B
__global__ __launch_bounds__(512,1) void sg6_kernel(Ptr5 xs, const float* __restrict__ cbv,
                                                    int b, int s){
    extern __shared__ uint32_t su[];
    uint32_t* AHb[2]={su,         su + SGB};
    uint32_t* ALb[2]={su + 2*SGB, su + 3*SGB};
    uint32_t* BHb[2]={su + 4*SGB, su + 5*SGB};
    uint32_t* BLb[2]={su + 6*SGB, su + 7*SGB};
    const int tid = threadIdx.x;
    const int h0 = blockIdx.x, img = blockIdx.y, pb = h0*128;
    const float* x = xs.p[img];
    const float* offs = g_offs + (size_t)img*HW*18;
    const float* mkb  = g_maskb + (size_t)img*HW*9;
    const int px = tid>>2, q4 = tid&3;
    const int wid = tid>>5, lane = tid&31, lg = lane>>2, lc = lane&3;
    const int warpM = wid&3, warpN = wid>>2;

    float d[2][4][4];
#pragma unroll
    for (int mt=0;mt<2;mt++)
#pragma unroll
        for (int nt=0;nt<4;nt++)
#pragma unroll
            for (int i=0;i<4;i++) d[mt][nt][i]=0.f;

    float w00=0.f,w01=0.f,w10=0.f,w11=0.f,mk=0.f;
    const float *c00=x,*c01=x,*c10=x,*c11=x;
    int pk = -1;
    float4 gr[8];
    uint4 wbh, wbl;

    auto compute_tap = [&](int k){
        int p = pb + px;
        float offy = offs[p*18 + 2*k];
        float offx = offs[p*18 + 2*k + 1];
        mk = mkb[p*9 + k];
        float py  = (float)(h0 - 1 + k/3) + offy;
        float pxf = (float)(px - 1 + (k - (k/3)*3)) + offx;
        float y0f = floorf(py), x0f = floorf(pxf);
        int y0 = (int)y0f, x0i = (int)x0f;
        float wy1 = py - y0f, wy0 = 1.f - wy1;
        float wx1 = pxf - x0f, wx0 = 1.f - wx1;
        int y1 = y0+1, x1i = x0i+1;
        bool vy0 = (y0>=0)&(y0<Hh), vy1 = (y1>=0)&(y1<Hh);
        bool vx0 = (x0i>=0)&(x0i<Ww), vx1 = (x1i>=0)&(x1i<Ww);
        w00 = (vy0&&vx0)? wy0*wx0 : 0.f;
        w01 = (vy0&&vx1)? wy0*wx1 : 0.f;
        w10 = (vy1&&vx0)? wy1*wx0 : 0.f;
        w11 = (vy1&&vx1)? wy1*wx1 : 0.f;
        int y0c = min(max(y0,0),Hh-1), y1c = min(max(y1,0),Hh-1);
        int x0c = min(max(x0i,0),Ww-1), x1c = min(max(x1i,0),Ww-1);
        c00 = x + (((y0c<<7)+x0c)<<7);
        c01 = x + (((y0c<<7)+x1c)<<7);
        c10 = x + (((y1c<<7)+x0c)<<7);
        c11 = x + (((y1c<<7)+x1c)<<7);
    };
    auto gather = [&](int it){
        int k = it>>2, cc = it&3;
        if (k != pk){ compute_tap(k); pk = k; }
        int cg = cc*32 + q4*8;
        gr[0]=((const float4*)(c00+cg))[0]; gr[1]=((const float4*)(c00+cg))[1];
        gr[2]=((const float4*)(c01+cg))[0]; gr[3]=((const float4*)(c01+cg))[1];
        gr[4]=((const float4*)(c10+cg))[0]; gr[5]=((const float4*)(c10+cg))[1];
        gr[6]=((const float4*)(c11+cg))[0]; gr[7]=((const float4*)(c11+cg))[1];
        uint32_t base = (uint32_t)(((k*4+cc)*128 + px)*16 + q4*4);
        wbh = *(const uint4*)(&g_wtPh[b][base]);
        wbl = *(const uint4*)(&g_wtPl[b][base]);
    };
    auto store_stage = [&](int buf){
        uint32_t hh[4], ll[4];
#pragma unroll
        for (int i=0;i<2;i++){
            float4 a = gr[i], b4 = gr[2+i], c4 = gr[4+i], e4 = gr[6+i];
            float4 o;
            o.x = mk*(w00*a.x + w01*b4.x + w10*c4.x + w11*e4.x);
            o.y = mk*(w00*a.y + w01*b4.y + w10*c4.y + w11*e4.y);
            o.z = mk*(w00*a.z + w01*b4.z + w10*c4.z + w11*e4.z);
            o.w = mk*(w00*a.w + w01*b4.w + w10*c4.w + w11*e4.w);
            bsplit2(make_float2(o.x,o.y), hh[i*2],   ll[i*2]);
            bsplit2(make_float2(o.z,o.w), hh[i*2+1], ll[i*2+1]);
        }
        uint32_t abase = (uint32_t)px*20 + q4*4;
        *(uint4*)(AHb[buf]+abase) = make_uint4(hh[0],hh[1],hh[2],hh[3]);
        *(uint4*)(ALb[buf]+abase) = make_uint4(ll[0],ll[1],ll[2],ll[3]);
        *(uint4*)(BHb[buf]+abase) = wbh;
        *(uint4*)(BLb[buf]+abase) = wbl;
    };

    gather(0); store_stage(0);
    __syncthreads();
    for (int it=0; it<36; it++){
        if (it < 35) gather(it+1);
        mma_chunk3(d, AHb[it&1], ALb[it&1], BHb[it&1], BLb[it&1], warpM, warpN, lg, lc);
        if (it < 35) store_stage((it+1)&1);
        __syncthreads();
    }

    // epilogue: bias + g_pre + fused stats
    float* Vs  = (float*)su;        // [128][132]
    float* Ps  = Vs + 16896;
    float* Ps2 = Ps + 512;
#pragma unroll
    for (int mt=0;mt<2;mt++){
        int r0 = warpM*32 + mt*16 + lg;
#pragma unroll
        for (int nt=0;nt<4;nt++){
            int co0 = warpN*32 + nt*8 + lc*2;
            float b0v = cbv[co0], b1v = cbv[co0+1];
            *(float2*)(Vs + r0*132 + co0)     = make_float2(d[mt][nt][0]+b0v, d[mt][nt][1]+b1v);
            *(float2*)(Vs + (r0+8)*132 + co0) = make_float2(d[mt][nt][2]+b0v, d[mt][nt][3]+b1v);
        }
    }
    __syncthreads();
    float* preo = g_pre + (size_t)img*HW*C;
#pragma unroll
    for (int t=0;t<32;t++){
        int idx = tid + t*512;
        int p2 = idx>>7, co = idx&127;
        preo[(pb+p2)*C + co] = Vs[p2*132 + co];
    }
    {
        int co = tid&127, qq = tid>>7;
        float S=0.f, Q=0.f;
#pragma unroll 8
        for (int i=0;i<32;i++){ float v = Vs[(qq*32+i)*132+co]; S += v; Q += v*v; }
        Ps[qq*128+co] = S; Ps2[qq*128+co] = Q;
        __syncthreads();
        if (tid < 128){
            float SS = Ps[tid]+Ps[128+tid]+Ps[256+tid]+Ps[384+tid];
            float QQ = Ps2[tid]+Ps2[128+tid]+Ps2[256+tid]+Ps2[384+tid];
            atomicAdd(&g_sumA[(s*NIMG+img)*128+tid], SS);
            atomicAdd(&g_sqA[(s*NIMG+img)*128+tid], QQ);
        }
    }
}

// ---------------- instance-norm apply ----------------
__global__ void normrelu2_kernel(const float* __restrict__ bg, const float* __restrict__ bb,
                                 float* __restrict__ outbase, int s){
    int img = blockIdx.y;
    int idx = blockIdx.x*blockDim.x + threadIdx.x;
    int c = idx & 127;
    float mu = g_sumA[(s*NIMG+img)*128+c] * (1.f/HW);
    float var = g_sqA[(s*NIMG+img)*128+c] * (1.f/HW) - mu*mu;
    float v = (g_pre[(size_t)img*HW*C + idx]-mu)*rsqrtf(var+EPS)*bg[c] + bb[c];
    outbase[(size_t)img*HW*C + idx] = fmaxf(v, 0.f);
}

// ---------------- projections via HMMA (K=256: xc || xp) ----------------
#define PJ_SMEM (8*SGB*4)
__global__ __launch_bounds__(512,1) void projH_kernel(const float* __restrict__ xcbase, Ptr5 xps,
                                                      float* __restrict__ out){
    const int img = blockIdx.z;
    const int nco = c_ncos[img];
    const int ct = blockIdx.y;
    if (ct*128 >= nco) return;
    extern __shared__ uint32_t su[];
    uint32_t* AHb[2]={su,         su + SGB};
    uint32_t* ALb[2]={su + 2*SGB, su + 3*SGB};
    uint32_t* BHb[2]={su + 4*SGB, su + 5*SGB};
    uint32_t* BLb[2]={su + 6*SGB, su + 7*SGB};
    const int tid = threadIdx.x;
    const int h0 = blockIdx.x, pb = h0*128;
    const float* xc = xcbase + (size_t)img*HW*C;
    const float* xp = xps.p[img];
    const int px = tid>>2, q4 = tid&3;
    const int wid = tid>>5, lane = tid&31, lg = lane>>2, lc = lane&3;
    const int warpM = wid&3, warpN = wid>>2;
    const int rowbase = c_pjbase[img] + ct*128;

    float d[2][4][4];
#pragma unroll
    for (int mt=0;mt<2;mt++)
#pragma unroll
        for (int nt=0;nt<4;nt++)
#pragma unroll
            for (int i=0;i<4;i++) d[mt][nt][i]=0.f;

    float4 gr[2];
    uint4 wbh, wbl;
    auto load_chunk = [&](int cc){
        const float* src = (cc<4) ? (xc + (size_t)(pb+px)*C + cc*32 + q4*8)
                                  : (xp + (size_t)(pb+px)*C + (cc-4)*32 + q4*8);
        gr[0] = ((const float4*)src)[0];
        gr[1] = ((const float4*)src)[1];
        uint32_t base = (uint32_t)((rowbase+px)*128 + cc*16 + q4*4);
        wbh = *(const uint4*)(&g_pjH[base]);
        wbl = *(const uint4*)(&g_pjL[base]);
    };
    auto store_stage = [&](int buf){
        uint32_t hh[4], ll[4];
        bsplit2(make_float2(gr[0].x,gr[0].y), hh[0], ll[0]);
        bsplit2(make_float2(gr[0].z,gr[0].w), hh[1], ll[1]);
        bsplit2(make_float2(gr[1].x,gr[1].y), hh[2], ll[2]);
        bsplit2(make_float2(gr[1].z,gr[1].w), hh[3], ll[3]);
        uint32_t abase = (uint32_t)px*20 + q4*4;
        *(uint4*)(AHb[buf]+abase) = make_uint4(hh[0],hh[1],hh[2],hh[3]);
        *(uint4*)(ALb[buf]+abase) = make_uint4(ll[0],ll[1],ll[2],ll[3]);
        *(uint4*)(BHb[buf]+abase) = wbh;
        *(uint4*)(BLb[buf]+abase) = wbl;
    };

    load_chunk(0); store_stage(0);
    __syncthreads();
    for (int cc=0; cc<8; cc++){
        if (cc < 7) load_chunk(cc+1);
        mma_chunk3(d, AHb[cc&1], ALb[cc&1], BHb[cc&1], BLb[cc&1], warpM, warpN, lg, lc);
        if (cc < 7) store_stage((cc+1)&1);
        __syncthreads();
    }

    float* Vs = (float*)su;   // [128][132]
#pragma unroll
    for (int mt=0;mt<2;mt++){
        int r0 = warpM*32 + mt*16 + lg;
#pragma unroll
        for (int nt=0;nt<4;nt++){
            int co0 = warpN*32 + nt*8 + lc*2;
            *(float2*)(Vs + r0*132 + co0)     = make_float2(d[mt][nt][0], d[mt][nt][1]);
            *(float2*)(Vs + (r0+8)*132 + co0) = make_float2(d[mt][nt][2], d[mt][nt][3]);
        }
    }
    __syncthreads();
    {
        int co = tid>>2, sub = tid&3;
        int cog = ct*128 + co;
        if (cog < nco){
            float* dst = out + (size_t)(c_coff[img]+cog)*HW + pb + sub*32;
#pragma unroll
            for (int j=0;j<8;j++){
                int r = sub*32 + j*4;
                float4 o = make_float4(Vs[r*132+co], Vs[(r+1)*132+co],
                                       Vs[(r+2)*132+co], Vs[(r+3)*132+co]);
                *(float4*)(dst + j*4) = o;
            }
        }
    }
}

// ---------------- final layernorm over W ----------------
__global__ __launch_bounds__(128) void ln_kernel(float* __restrict__ o, const float* __restrict__ lnw,
                                                 const float* __restrict__ lnb){
    __shared__ float ss[4], ssq[4];
    int row = blockIdx.x;
    float* r = o + (size_t)row*128;
    int t = threadIdx.x;
    float v = r[t];
    float s = v, sq = v*v;
#pragma unroll
    for (int off=16; off; off>>=1){
        s  += __shfl_down_sync(0xffffffffu, s, off);
        sq += __shfl_down_sync(0xffffffffu, sq, off);
    }
    int wid = t >> 5, lane = t & 31;
    if (lane==0){ ss[wid]=s; ssq[wid]=sq; }
    __syncthreads();
    float S  = ss[0]+ss[1]+ss[2]+ss[3];
    float SQ = ssq[0]+ssq[1]+ssq[2]+ssq[3];
    float mu = S*(1.f/128.f);
    float var = SQ*(1.f/128.f) - mu*mu;
    r[t] = (v-mu)*rsqrtf(var+EPS)*lnw[t] + lnb[t];
}

// ---------------- host orchestration ----------------
extern "C" void kernel_launch(void* const* d_in, const int* in_sizes, int n_in,
                              void* d_out, int out_size){
    (void)in_sizes; (void)n_in; (void)out_size;
    const float* x[5];
    for (int i=0;i<5;i++) x[i] = (const float*)d_in[i];
    const float* cw[2] = {(const float*)d_in[5],  (const float*)d_in[11]};
    const float* cb[2] = {(const float*)d_in[6],  (const float*)d_in[12]};
    const float* ow[2] = {(const float*)d_in[7],  (const float*)d_in[13]};
    const float* mw[2] = {(const float*)d_in[8],  (const float*)d_in[14]};
    const float* bg[2] = {(const float*)d_in[9],  (const float*)d_in[15]};
    const float* bb[2] = {(const float*)d_in[10], (const float*)d_in[16]};
    const float* pwa[5] = {(const float*)d_in[17], (const float*)d_in[18], (const float*)d_in[19],
                           (const float*)d_in[21], (const float*)d_in[23]};
    const float* pwb[5] = {nullptr, nullptr, (const float*)d_in[20],
                           (const float*)d_in[22], (const float*)d_in[24]};
    const float* lnw = (const float*)d_in[25];
    const float* lnb = (const float*)d_in[26];
    float* outp = (float*)d_out;

    float *pA=nullptr, *pB=nullptr;
    cudaGetSymbolAddress((void**)&pA, g_bufA);
    cudaGetSymbolAddress((void**)&pB, g_bufB);

    Ptr5 xs0, xsA, wav, wbv;
    for (int i=0;i<5;i++){
        xs0.p[i] = x[i];
        xsA.p[i] = pA + (size_t)i*HW*C;
        wav.p[i] = pwa[i];
        wbv.p[i] = pwb[i];
    }

    cudaFuncSetAttribute(offcv3_kernel, cudaFuncAttributeMaxDynamicSharedMemorySize, OC_SMEM);
    cudaFuncSetAttribute(sg6_kernel, cudaFuncAttributeMaxDynamicSharedMemorySize, SG6_SMEM);
    cudaFuncSetAttribute(projH_kernel, cudaFuncAttributeMaxDynamicSharedMemorySize, PJ_SMEM);

    prep_wtP_kernel<<<(KK*4*128*16+255)/256, 256>>>(cw[0], cw[1]);
    prep_effP_kernel<<<(KK*4*32*16+255)/256, 256>>>(cw[0], ow[0], mw[0], cb[0], 0);
    prep_effP_kernel<<<(KK*4*32*16+255)/256, 256>>>(cw[1], ow[1], mw[1], cb[1], 1);
    prep_pj_kernel<<<(1280*128+255)/256, 256>>>(wav, wbv);
    zero_sums_kernel<<<5, 256>>>();

    // stage 1 (all images)
    offcv3_kernel<<<dim3(128,5), 256, OC_SMEM>>>(xs0, 0);
    sg6_kernel<<<dim3(128,5), 512, SG6_SMEM>>>(xs0, cb[0], 0, 0);
    normrelu2_kernel<<<dim3(HW*C/256,5), 256>>>(bg[0], bb[0], pA, 0);
    // stage 2 (all images)
    offcv3_kernel<<<dim3(128,5), 256, OC_SMEM>>>(xsA, 1);
    sg6_kernel<<<dim3(128,5), 512, SG6_SMEM>>>(xsA, cb[1], 1, 1);
    normrelu2_kernel<<<dim3(HW*C/256,5), 256>>>(bg[1], bb[1], pB, 1);
    // projections + final LN
    projH_kernel<<<dim3(128,3,5), 512, PJ_SMEM>>>(pB, xs0, outp);
    ln_kernel<<<768*Hh, 128>>>(outp, lnw, lnb);
}

// round 10
// speedup vs baseline: 2.8618x; 1.0651x over previous
#include <cuda_runtime.h>
#include <cuda_bf16.h>
#include <cstdint>

#define Hh 128
#define Ww 128
#define HW 16384
#define C 128
#define KK 9
#define EPS 1e-5f
#define NIMG 5

struct Ptr5 { const float* p[NIMG]; };

// ---------------- scratch (device globals; no runtime alloc) ----------------
__device__ float g_bufA[NIMG*HW*C];
__device__ float g_bufB[NIMG*HW*C];
__device__ float g_pre[NIMG*HW*C];
__device__ float g_offs[NIMG*HW*18];
__device__ float g_maskb[NIMG*HW*9];
__device__ uint32_t g_wtPh[2][KK*4*128*16];   // [b][k][cc][co][pair] bf16x2 hi
__device__ uint32_t g_wtPl[2][KK*4*128*16];
__device__ uint32_t g_effPh[2][KK*4*32*16];   // [b][k][cc][j][pair] bf16x2 hi
__device__ uint32_t g_effPl[2][KK*4*32*16];
__device__ float g_effb[2][32];
__device__ uint32_t g_pjH[1280*128];          // proj weights bf16x2 hi (K=256)
__device__ uint32_t g_pjL[1280*128];
__device__ float g_sumA[2*NIMG*128];
__device__ float g_sqA[2*NIMG*128];

__constant__ int c_ncos[5]   = {20,80,150,210,308};
__constant__ int c_pjbase[5] = {0,128,256,512,896};
__constant__ int c_coff[5]   = {0,20,100,250,460};
__constant__ int c_ccend[5]  = {4,4,8,8,8};

// ---------------- helpers ----------------
__device__ __forceinline__ void bsplit2(float2 v, uint32_t &hp, uint32_t &lp_){
    __nv_bfloat162 h2 = __float22bfloat162_rn(v);
    float2 hf = __bfloat1622float2(h2);
    __nv_bfloat162 l2 = __float22bfloat162_rn(make_float2(v.x - hf.x, v.y - hf.y));
    hp = *reinterpret_cast<uint32_t*>(&h2);
    lp_ = *reinterpret_cast<uint32_t*>(&l2);
}
__device__ __forceinline__ void mma_bf16(float* d, uint32_t a0,uint32_t a1,uint32_t a2,uint32_t a3,
                                         uint32_t b0, uint32_t b1){
    asm volatile("mma.sync.aligned.m16n8k16.row.col.f32.bf16.bf16.f32 "
        "{%0,%1,%2,%3}, {%4,%5,%6,%7}, {%8,%9}, {%0,%1,%2,%3};"
        : "+f"(d[0]),"+f"(d[1]),"+f"(d[2]),"+f"(d[3])
        : "r"(a0),"r"(a1),"r"(a2),"r"(a3),"r"(b0),"r"(b1));
}

// 3-pass bf16-split MMA over one K=32 chunk; A/B smem stride 20 u32 per row.
__device__ __forceinline__ void mma_chunk3(float d[2][4][4],
    const uint32_t* __restrict__ AH, const uint32_t* __restrict__ AL,
    const uint32_t* __restrict__ BH, const uint32_t* __restrict__ BL,
    int warpM, int warpN, int lg, int lc){
#pragma unroll
    for (int ks=0; ks<2; ks++){
        uint32_t ah[2][4], al[2][4];
#pragma unroll
        for (int mt=0;mt<2;mt++){
            uint32_t base = (uint32_t)(warpM*32+mt*16+lg)*20 + ks*8 + lc;
            ah[mt][0]=AH[base]; ah[mt][1]=AH[base+160]; ah[mt][2]=AH[base+4]; ah[mt][3]=AH[base+164];
            al[mt][0]=AL[base]; al[mt][1]=AL[base+160]; al[mt][2]=AL[base+4]; al[mt][3]=AL[base+164];
        }
        uint32_t bh[4][2];
#pragma unroll
        for (int nt=0;nt<4;nt++){
            uint32_t bb = (uint32_t)(warpN*32+nt*8+lg)*20 + ks*8 + lc;
            bh[nt][0]=BH[bb]; bh[nt][1]=BH[bb+4];
            mma_bf16(d[0][nt], ah[0][0],ah[0][1],ah[0][2],ah[0][3], bh[nt][0],bh[nt][1]);
            mma_bf16(d[1][nt], ah[1][0],ah[1][1],ah[1][2],ah[1][3], bh[nt][0],bh[nt][1]);
        }
#pragma unroll
        for (int nt=0;nt<4;nt++){
            uint32_t bb = (uint32_t)(warpN*32+nt*8+lg)*20 + ks*8 + lc;
            uint32_t b0=BL[bb], b1=BL[bb+4];
            mma_bf16(d[0][nt], ah[0][0],ah[0][1],ah[0][2],ah[0][3], b0,b1);
            mma_bf16(d[1][nt], ah[1][0],ah[1][1],ah[1][2],ah[1][3], b0,b1);
        }
#pragma unroll
        for (int nt=0;nt<4;nt++){
            mma_bf16(d[0][nt], al[0][0],al[0][1],al[0][2],al[0][3], bh[nt][0],bh[nt][1]);
            mma_bf16(d[1][nt], al[1][0],al[1][1],al[1][2],al[1][3], bh[nt][0],bh[nt][1]);
        }
    }
}

// ---------------- prep kernels ----------------
__global__ void prep_wtP_kernel(const float* __restrict__ cw0, const float* __restrict__ cw1){
    int idx = blockIdx.x*blockDim.x + threadIdx.x;
    if (idx >= KK*4*128*16) return;
    int pr = idx & 15, co = (idx>>4)&127, cc = (idx>>11)&3, k = idx>>13;
    int ci0 = cc*32 + pr*2;
    uint32_t hp, lp;
    bsplit2(make_float2(cw0[(co*C+ci0)*KK + k], cw0[(co*C+ci0+1)*KK + k]), hp, lp);
    g_wtPh[0][idx]=hp; g_wtPl[0][idx]=lp;
    bsplit2(make_float2(cw1[(co*C+ci0)*KK + k], cw1[(co*C+ci0+1)*KK + k]), hp, lp);
    g_wtPh[1][idx]=hp; g_wtPl[1][idx]=lp;
}

__global__ void prep_effP_kernel(const float* __restrict__ cw, const float* __restrict__ ow,
                                 const float* __restrict__ mw, const float* __restrict__ cb, int b){
    int idx = blockIdx.x*blockDim.x + threadIdx.x;
    if (idx >= KK*4*32*16) return;
    int pr = idx&15, j = (idx>>4)&31, cc=(idx>>9)&3, k=idx>>11;
    int ci0 = cc*32 + pr*2;
    float s0=0.f, s1=0.f;
    if (j < 27){
        const float* P = (j<18) ? (ow + j*C) : (mw + (j-18)*C);
        for (int co=0; co<C; co++){
            float p = P[co];
            s0 += p*cw[(co*C+ci0)*KK + k];
            s1 += p*cw[(co*C+ci0+1)*KK + k];
        }
    }
    uint32_t hp, lp;
    bsplit2(make_float2(s0,s1), hp, lp);
    g_effPh[b][idx]=hp; g_effPl[b][idx]=lp;
    if (idx < 32){
        float bbv = 0.f;
        if (idx < 27){
            const float* P = (idx<18) ? (ow + idx*C) : (mw + (idx-18)*C);
            for (int co=0; co<C; co++) bbv += P[co]*cb[co];
        }
        g_effb[b][idx] = bbv;
    }
}

__global__ void prep_pj_kernel(Ptr5 wa, Ptr5 wb){
    int idx = blockIdx.x*blockDim.x + threadIdx.x;
    if (idx >= 1280*128) return;
    int u = idx & 127, row = idx >> 7;
    int img = 0;
#pragma unroll
    for (int i=1;i<5;i++) if (row >= c_pjbase[i]) img = i;
    int lco = row - c_pjbase[img];
    float v0=0.f, v1=0.f;
    if (lco < c_ncos[img]){
        if (u < 64){
            const float* w = wa.p[img];
            v0 = w[lco*C + u*2]; v1 = w[lco*C + u*2+1];
        } else {
            const float* w = wb.p[img];
            if (w){ v0 = w[lco*C + (u-64)*2]; v1 = w[lco*C + (u-64)*2+1]; }
        }
    }
    uint32_t hp, lp;
    bsplit2(make_float2(v0,v1), hp, lp);
    g_pjH[idx]=hp; g_pjL[idx]=lp;
}

__global__ void zero_sums_kernel(){
    int t = blockIdx.x*blockDim.x + threadIdx.x;
    if (t < 2*NIMG*128){ g_sumA[t]=0.f; g_sqA[t]=0.f; }
}

// ---------------- offsets conv via bf16 3-pass HMMA (PROVEN R7 version) ----------------
#define OC_SMEM (25560*4)
__global__ __launch_bounds__(256) void offcv3_kernel(Ptr5 xs, int b){
    extern __shared__ uint32_t su[];
    uint32_t* RH = su;
    uint32_t* RL = su + 7020;
    uint32_t* BOH = su + 14040;
    uint32_t* BOL = su + 19800;
    const int tid = threadIdx.x;
    const int h0 = blockIdx.x, img = blockIdx.y, pb = h0*128;
    const float* x = xs.p[img];
    float* offs = g_offs + (size_t)img*HW*18;
    float* mkb  = g_maskb + (size_t)img*HW*9;
    const int wid = tid>>5, lane = tid&31, lg = lane>>2, lc = lane&3;
    float d[4][4];
#pragma unroll
    for (int nt=0;nt<4;nt++)
#pragma unroll
        for (int i=0;i<4;i++) d[nt][i]=0.f;

    for (int cc=0; cc<4; cc++){
        __syncthreads();
#pragma unroll
        for (int t=0;t<2;t++){
            int idx = tid + t*256;
            if (idx < 384){
                int r = idx>>7, px = idx&127;
                int hh = h0 + r - 1;
                uint32_t base = (uint32_t)(r*130 + px + 1)*18;
                if (hh>=0 && hh<Hh){
                    const float4* src = (const float4*)(x + (((hh<<7)+px)<<7) + cc*32);
#pragma unroll
                    for (int i=0;i<8;i++){
                        float4 v = src[i];
                        uint32_t h0p,l0p,h1p,l1p;
                        bsplit2(make_float2(v.x,v.y), h0p,l0p);
                        bsplit2(make_float2(v.z,v.w), h1p,l1p);
                        *(uint2*)(RH + base + i*2) = make_uint2(h0p,h1p);
                        *(uint2*)(RL + base + i*2) = make_uint2(l0p,l1p);
                    }
                } else {
#pragma unroll
                    for (int i=0;i<8;i++){
                        *(uint2*)(RH + base + i*2) = make_uint2(0u,0u);
                        *(uint2*)(RL + base + i*2) = make_uint2(0u,0u);
                    }
                }
            }
        }
        if (tid < 96){
            int slot = tid>>4, pr = tid&15;
            int r = slot>>1, side = slot&1;
            uint32_t base = (uint32_t)(r*130 + (side?129:0))*18;
            RH[base+pr]=0u; RL[base+pr]=0u;
        }
#pragma unroll
        for (int t=0;t<18;t++){
            int idx = tid + t*256;
            int k = idx>>9, rr = idx & 511;
            int j = rr>>4, pr = rr&15;
            uint32_t gidx = (uint32_t)((k*4+cc)<<9) + (uint32_t)rr;
            BOH[(uint32_t)(k*32+j)*20 + pr] = g_effPh[b][gidx];
            BOL[(uint32_t)(k*32+j)*20 + pr] = g_effPl[b][gidx];
        }
        __syncthreads();
        for (int k=0;k<KK;k++){
            int ky = k/3, kx = k - ky*3 - 1;
#pragma unroll
            for (int ks=0; ks<2; ks++){
                uint32_t row = (uint32_t)(wid*16 + lg + kx + 1);
                uint32_t abase = ((uint32_t)ky*130 + row)*18 + ks*8 + lc;
                uint32_t ah0 = RH[abase],      ah1 = RH[abase + 144];
                uint32_t ah2 = RH[abase + 4],  ah3 = RH[abase + 148];
                uint32_t al0 = RL[abase],      al1 = RL[abase + 144];
                uint32_t al2 = RL[abase + 4],  al3 = RL[abase + 148];
#pragma unroll
                for (int nt=0;nt<4;nt++){
                    uint32_t bb = (uint32_t)(k*32 + nt*8 + lg)*20 + ks*8 + lc;
                    uint32_t b0 = BOH[bb], b1 = BOH[bb+4];
                    mma_bf16(d[nt], ah0,ah1,ah2,ah3, b0,b1);
                }
#pragma unroll
                for (int nt=0;nt<4;nt++){
                    uint32_t bb = (uint32_t)(k*32 + nt*8 + lg)*20 + ks*8 + lc;
                    uint32_t b0 = BOL[bb], b1 = BOL[bb+4];
                    mma_bf16(d[nt], ah0,ah1,ah2,ah3, b0,b1);
                }
#pragma unroll
                for (int nt=0;nt<4;nt++){
                    uint32_t bb = (uint32_t)(k*32 + nt*8 + lg)*20 + ks*8 + lc;
                    uint32_t b0 = BOH[bb], b1 = BOH[bb+4];
                    mma_bf16(d[nt], al0,al1,al2,al3, b0,b1);
                }
            }
        }
    }
    __syncthreads();
    float* Vs = (float*)su;  // [128][33]
#pragma unroll
    for (int nt=0;nt<4;nt++){
        int col = nt*8 + lc*2;
        int r0 = wid*16 + lg;
        Vs[r0*33 + col]       = d[nt][0] + g_effb[b][col];
        Vs[r0*33 + col + 1]   = d[nt][1] + g_effb[b][col+1];
        Vs[(r0+8)*33 + col]   = d[nt][2] + g_effb[b][col];
        Vs[(r0+8)*33 + col+1] = d[nt][3] + g_effb[b][col+1];
    }
    __syncthreads();
    if (tid < 128){
        int p = pb + tid;
        const float* v = Vs + tid*33;
#pragma unroll
        for (int j=0;j<18;j++) offs[p*18+j] = v[j];
        float mx = v[18];
#pragma unroll
        for (int j=19;j<27;j++) mx = fmaxf(mx, v[j]);
        float e[9]; float smv = 0.f;
#pragma unroll
        for (int j=0;j<9;j++){ e[j] = expf(v[18+j]-mx); smv += e[j]; }
        float inv = 1.f/smv;
#pragma unroll
        for (int j=0;j<9;j++) mkb[p*9+j] = e[j]*inv;
    }
}

// ---------------- pipelined sample-GEMM (coalesced q8 gather) ----------------
#define SGB 2560
#define SG7_SMEM (8*SGB*4)   // 81920 B
__global__ __launch_bounds__(512,1) void sg7_kernel(Ptr5 xs, const float* __restrict__ cbv,
                                                    int b, int s){
    extern __shared__ uint32_t su[];
    uint32_t* AHb[2]={su,         su + SGB};
    uint32_t* ALb[2]={su + 2*SGB, su + 3*SGB};
    uint32_t* BHb[2]={su + 4*SGB, su + 5*SGB};
    uint32_t* BLb[2]={su + 6*SGB, su + 7*SGB};
    const int tid = threadIdx.x;
    const int h0 = blockIdx.x, img = blockIdx.y, pb = h0*128;
    const float* x = xs.p[img];
    const float* offs = g_offs + (size_t)img*HW*18;
    const float* mkb  = g_maskb + (size_t)img*HW*9;
    const int q8 = tid & 7, pxA = tid >> 3;      // 2 px per thread: pxA, pxA+64
    const int cob = tid >> 2, qb = tid & 3;      // B staging roles
    const int wid = tid>>5, lane = tid&31, lg = lane>>2, lc = lane&3;
    const int warpM = wid&3, warpN = wid>>2;

    float d[2][4][4];
#pragma unroll
    for (int mt=0;mt<2;mt++)
#pragma unroll
        for (int nt=0;nt<4;nt++)
#pragma unroll
            for (int i=0;i<4;i++) d[mt][nt][i]=0.f;

    float w00[2],w01[2],w10[2],w11[2],mk[2];
    int roff[2][4];
    int pk = -1;
    float4 gr[2][4];
    uint4 wbh, wbl;

    auto compute_tap = [&](int k){
#pragma unroll
        for (int sl=0; sl<2; sl++){
            int px = pxA + sl*64;
            int p = pb + px;
            float offy = offs[p*18 + 2*k];
            float offx = offs[p*18 + 2*k + 1];
            mk[sl] = mkb[p*9 + k];
            float py  = (float)(h0 - 1 + k/3) + offy;
            float pxf = (float)(px - 1 + (k - (k/3)*3)) + offx;
            float y0f = floorf(py), x0f = floorf(pxf);
            int y0 = (int)y0f, x0i = (int)x0f;
            float wy1 = py - y0f, wy0 = 1.f - wy1;
            float wx1 = pxf - x0f, wx0 = 1.f - wx1;
            int y1 = y0+1, x1i = x0i+1;
            bool vy0 = (y0>=0)&(y0<Hh), vy1 = (y1>=0)&(y1<Hh);
            bool vx0 = (x0i>=0)&(x0i<Ww), vx1 = (x1i>=0)&(x1i<Ww);
            w00[sl] = (vy0&&vx0)? wy0*wx0 : 0.f;
            w01[sl] = (vy0&&vx1)? wy0*wx1 : 0.f;
            w10[sl] = (vy1&&vx0)? wy1*wx0 : 0.f;
            w11[sl] = (vy1&&vx1)? wy1*wx1 : 0.f;
            int y0c = min(max(y0,0),Hh-1), y1c = min(max(y1,0),Hh-1);
            int x0c = min(max(x0i,0),Ww-1), x1c = min(max(x1i,0),Ww-1);
            roff[sl][0] = ((y0c<<7)+x0c)<<7;
            roff[sl][1] = ((y0c<<7)+x1c)<<7;
            roff[sl][2] = ((y1c<<7)+x0c)<<7;
            roff[sl][3] = ((y1c<<7)+x1c)<<7;
        }
    };
    auto gather = [&](int it){
        int k = it>>2, cc = it&3;
        if (k != pk){ compute_tap(k); pk = k; }
        int cg = cc*32 + q8*4;
#pragma unroll
        for (int sl=0; sl<2; sl++)
#pragma unroll
            for (int c=0; c<4; c++)
                gr[sl][c] = *(const float4*)(x + roff[sl][c] + cg);
        uint32_t base = (uint32_t)(((k*4+cc)*128 + cob)*16 + qb*4);
        wbh = *(const uint4*)(&g_wtPh[b][base]);
        wbl = *(const uint4*)(&g_wtPl[b][base]);
    };
    auto store_stage = [&](int buf){
#pragma unroll
        for (int sl=0; sl<2; sl++){
            float4 a = gr[sl][0], b4 = gr[sl][1], c4 = gr[sl][2], e4 = gr[sl][3];
            float4 o;
            o.x = mk[sl]*(w00[sl]*a.x + w01[sl]*b4.x + w10[sl]*c4.x + w11[sl]*e4.x);
            o.y = mk[sl]*(w00[sl]*a.y + w01[sl]*b4.y + w10[sl]*c4.y + w11[sl]*e4.y);
            o.z = mk[sl]*(w00[sl]*a.z + w01[sl]*b4.z + w10[sl]*c4.z + w11[sl]*e4.z);
            o.w = mk[sl]*(w00[sl]*a.w + w01[sl]*b4.w + w10[sl]*c4.w + w11[sl]*e4.w);
            uint32_t h0p,l0p,h1p,l1p;
            bsplit2(make_float2(o.x,o.y), h0p,l0p);
            bsplit2(make_float2(o.z,o.w), h1p,l1p);
            uint32_t abase = (uint32_t)(pxA + sl*64)*20 + q8*2;
            *(uint2*)(AHb[buf]+abase) = make_uint2(h0p,h1p);
            *(uint2*)(ALb[buf]+abase) = make_uint2(l0p,l1p);
        }
        uint32_t bbase = (uint32_t)cob*20 + qb*4;
        *(uint4*)(BHb[buf]+bbase) = wbh;
        *(uint4*)(BLb[buf]+bbase) = wbl;
    };

    gather(0);
    for (int it=0; it<36; it++){
        int buf = it & 1;
        store_stage(buf);
        __syncthreads();
        if (it < 35) gather(it+1);
        mma_chunk3(d, AHb[buf], ALb[buf], BHb[buf], BLb[buf], warpM, warpN, lg, lc);
    }
    __syncthreads();

    // epilogue: bias + g_pre + fused stats
    float* Vs  = (float*)su;        // [128][132]
    float* Ps  = Vs + 16896;
    float* Ps2 = Ps + 512;
#pragma unroll
    for (int mt=0;mt<2;mt++){
        int r0 = warpM*32 + mt*16 + lg;
#pragma unroll
        for (int nt=0;nt<4;nt++){
            int co0 = warpN*32 + nt*8 + lc*2;
            float b0v = cbv[co0], b1v = cbv[co0+1];
            *(float2*)(Vs + r0*132 + co0)     = make_float2(d[mt][nt][0]+b0v, d[mt][nt][1]+b1v);
            *(float2*)(Vs + (r0+8)*132 + co0) = make_float2(d[mt][nt][2]+b0v, d[mt][nt][3]+b1v);
        }
    }
    __syncthreads();
    float* preo = g_pre + (size_t)img*HW*C;
#pragma unroll
    for (int t=0;t<32;t++){
        int idx = tid + t*512;
        int p2 = idx>>7, co = idx&127;
        preo[(pb+p2)*C + co] = Vs[p2*132 + co];
    }
    {
        int co = tid&127, qq = tid>>7;
        float S=0.f, Q=0.f;
#pragma unroll 8
        for (int i=0;i<32;i++){ float v = Vs[(qq*32+i)*132+co]; S += v; Q += v*v; }
        Ps[qq*128+co] = S; Ps2[qq*128+co] = Q;
        __syncthreads();
        if (tid < 128){
            float SS = Ps[tid]+Ps[128+tid]+Ps[256+tid]+Ps[384+tid];
            float QQ = Ps2[tid]+Ps2[128+tid]+Ps2[256+tid]+Ps2[384+tid];
            atomicAdd(&g_sumA[(s*NIMG+img)*128+tid], SS);
            atomicAdd(&g_sqA[(s*NIMG+img)*128+tid], QQ);
        }
    }
}

// ---------------- instance-norm apply ----------------
__global__ void normrelu2_kernel(const float* __restrict__ bg, const float* __restrict__ bb,
                                 float* __restrict__ outbase, int s){
    int img = blockIdx.y;
    int idx = blockIdx.x*blockDim.x + threadIdx.x;
    int c = idx & 127;
    float mu = g_sumA[(s*NIMG+img)*128+c] * (1.f/HW);
    float var = g_sqA[(s*NIMG+img)*128+c] * (1.f/HW) - mu*mu;
    float v = (g_pre[(size_t)img*HW*C + idx]-mu)*rsqrtf(var+EPS)*bg[c] + bb[c];
    outbase[(size_t)img*HW*C + idx] = fmaxf(v, 0.f);
}

// ---------------- projections via HMMA (K=256: xc || xp; NCC skip for imgs 0/1) ----------------
#define PJ_SMEM (8*SGB*4)
__global__ __launch_bounds__(512,1) void projH_kernel(const float* __restrict__ xcbase, Ptr5 xps,
                                                      float* __restrict__ out){
    const int img = blockIdx.z;
    const int nco = c_ncos[img];
    const int ct = blockIdx.y;
    if (ct*128 >= nco) return;
    extern __shared__ uint32_t su[];
    uint32_t* AHb[2]={su,         su + SGB};
    uint32_t* ALb[2]={su + 2*SGB, su + 3*SGB};
    uint32_t* BHb[2]={su + 4*SGB, su + 5*SGB};
    uint32_t* BLb[2]={su + 6*SGB, su + 7*SGB};
    const int tid = threadIdx.x;
    const int h0 = blockIdx.x, pb = h0*128;
    const float* xc = xcbase + (size_t)img*HW*C;
    const float* xp = xps.p[img];
    const int px = tid>>2, q4 = tid&3;
    const int wid = tid>>5, lane = tid&31, lg = lane>>2, lc = lane&3;
    const int warpM = wid&3, warpN = wid>>2;
    const int rowbase = c_pjbase[img] + ct*128;
    const int NCC = c_ccend[img];

    float d[2][4][4];
#pragma unroll
    for (int mt=0;mt<2;mt++)
#pragma unroll
        for (int nt=0;nt<4;nt++)
#pragma unroll
            for (int i=0;i<4;i++) d[mt][nt][i]=0.f;

    float4 gr[2];
    uint4 wbh, wbl;
    auto load_chunk = [&](int cc){
        const float* src = (cc<4) ? (xc + (size_t)(pb+px)*C + cc*32 + q4*8)
                                  : (xp + (size_t)(pb+px)*C + (cc-4)*32 + q4*8);
        gr[0] = ((const float4*)src)[0];
        gr[1] = ((const float4*)src)[1];
        uint32_t base = (uint32_t)((rowbase+px)*128 + cc*16 + q4*4);
        wbh = *(const uint4*)(&g_pjH[base]);
        wbl = *(const uint4*)(&g_pjL[base]);
    };
    auto store_stage = [&](int buf){
        uint32_t hh[4], ll[4];
        bsplit2(make_float2(gr[0].x,gr[0].y), hh[0], ll[0]);
        bsplit2(make_float2(gr[0].z,gr[0].w), hh[1], ll[1]);
        bsplit2(make_float2(gr[1].x,gr[1].y), hh[2], ll[2]);
        bsplit2(make_float2(gr[1].z,gr[1].w), hh[3], ll[3]);
        uint32_t abase = (uint32_t)px*20 + q4*4;
        *(uint4*)(AHb[buf]+abase) = make_uint4(hh[0],hh[1],hh[2],hh[3]);
        *(uint4*)(ALb[buf]+abase) = make_uint4(ll[0],ll[1],ll[2],ll[3]);
        *(uint4*)(BHb[buf]+abase) = wbh;
        *(uint4*)(BLb[buf]+abase) = wbl;
    };

    load_chunk(0); store_stage(0);
    __syncthreads();
    for (int cc=0; cc<NCC; cc++){
        if (cc < NCC-1) load_chunk(cc+1);
        mma_chunk3(d, AHb[cc&1], ALb[cc&1], BHb[cc&1], BLb[cc&1], warpM, warpN, lg, lc);
        if (cc < NCC-1) store_stage((cc+1)&1);
        __syncthreads();
    }

    float* Vs = (float*)su;   // [128][132]
#pragma unroll
    for (int mt=0;mt<2;mt++){
        int r0 = warpM*32 + mt*16 + lg;
#pragma unroll
        for (int nt=0;nt<4;nt++){
            int co0 = warpN*32 + nt*8 + lc*2;
            *(float2*)(Vs + r0*132 + co0)     = make_float2(d[mt][nt][0], d[mt][nt][1]);
            *(float2*)(Vs + (r0+8)*132 + co0) = make_float2(d[mt][nt][2], d[mt][nt][3]);
        }
    }
    __syncthreads();
    {
        int co = tid>>2, sub = tid&3;
        int cog = ct*128 + co;
        if (cog < nco){
            float* dst = out + (size_t)(c_coff[img]+cog)*HW + pb + sub*32;
#pragma unroll
            for (int j=0;j<8;j++){
                int r = sub*32 + j*4;
                float4 o = make_float4(Vs[r*132+co], Vs[(r+1)*132+co],
                                       Vs[(r+2)*132+co], Vs[(r+3)*132+co]);
                *(float4*)(dst + j*4) = o;
            }
        }
    }
}

// ---------------- final layernorm over W ----------------
__global__ __launch_bounds__(128) void ln_kernel(float* __restrict__ o, const float* __restrict__ lnw,
                                                 const float* __restrict__ lnb){
    __shared__ float ss[4], ssq[4];
    int row = blockIdx.x;
    float* r = o + (size_t)row*128;
    int t = threadIdx.x;
    float v = r[t];
    float s = v, sq = v*v;
#pragma unroll
    for (int off=16; off; off>>=1){
        s  += __shfl_down_sync(0xffffffffu, s, off);
        sq += __shfl_down_sync(0xffffffffu, sq, off);
    }
    int wid = t >> 5, lane = t & 31;
    if (lane==0){ ss[wid]=s; ssq[wid]=sq; }
    __syncthreads();
    float S  = ss[0]+ss[1]+ss[2]+ss[3];
    float SQ = ssq[0]+ssq[1]+ssq[2]+ssq[3];
    float mu = S*(1.f/128.f);
    float var = SQ*(1.f/128.f) - mu*mu;
    r[t] = (v-mu)*rsqrtf(var+EPS)*lnw[t] + lnb[t];
}

// ---------------- host orchestration ----------------
extern "C" void kernel_launch(void* const* d_in, const int* in_sizes, int n_in,
                              void* d_out, int out_size){
    (void)in_sizes; (void)n_in; (void)out_size;
    const float* x[5];
    for (int i=0;i<5;i++) x[i] = (const float*)d_in[i];
    const float* cw[2] = {(const float*)d_in[5],  (const float*)d_in[11]};
    const float* cb[2] = {(const float*)d_in[6],  (const float*)d_in[12]};
    const float* ow[2] = {(const float*)d_in[7],  (const float*)d_in[13]};
    const float* mw[2] = {(const float*)d_in[8],  (const float*)d_in[14]};
    const float* bg[2] = {(const float*)d_in[9],  (const float*)d_in[15]};
    const float* bb[2] = {(const float*)d_in[10], (const float*)d_in[16]};
    const float* pwa[5] = {(const float*)d_in[17], (const float*)d_in[18], (const float*)d_in[19],
                           (const float*)d_in[21], (const float*)d_in[23]};
    const float* pwb[5] = {nullptr, nullptr, (const float*)d_in[20],
                           (const float*)d_in[22], (const float*)d_in[24]};
    const float* lnw = (const float*)d_in[25];
    const float* lnb = (const float*)d_in[26];
    float* outp = (float*)d_out;

    float *pA=nullptr, *pB=nullptr;
    cudaGetSymbolAddress((void**)&pA, g_bufA);
    cudaGetSymbolAddress((void**)&pB, g_bufB);

    Ptr5 xs0, xsA, wav, wbv;
    for (int i=0;i<5;i++){
        xs0.p[i] = x[i];
        xsA.p[i] = pA + (size_t)i*HW*C;
        wav.p[i] = pwa[i];
        wbv.p[i] = pwb[i];
    }

    cudaFuncSetAttribute(offcv3_kernel, cudaFuncAttributeMaxDynamicSharedMemorySize, OC_SMEM);
    cudaFuncSetAttribute(sg7_kernel, cudaFuncAttributeMaxDynamicSharedMemorySize, SG7_SMEM);
    cudaFuncSetAttribute(projH_kernel, cudaFuncAttributeMaxDynamicSharedMemorySize, PJ_SMEM);

    prep_wtP_kernel<<<(KK*4*128*16+255)/256, 256>>>(cw[0], cw[1]);
    prep_effP_kernel<<<(KK*4*32*16+255)/256, 256>>>(cw[0], ow[0], mw[0], cb[0], 0);
    prep_effP_kernel<<<(KK*4*32*16+255)/256, 256>>>(cw[1], ow[1], mw[1], cb[1], 1);
    prep_pj_kernel<<<(1280*128+255)/256, 256>>>(wav, wbv);
    zero_sums_kernel<<<5, 256>>>();

    // stage 1 (all images)
    offcv3_kernel<<<dim3(128,5), 256, OC_SMEM>>>(xs0, 0);
    sg7_kernel<<<dim3(128,5), 512, SG7_SMEM>>>(xs0, cb[0], 0, 0);
    normrelu2_kernel<<<dim3(HW*C/256,5), 256>>>(bg[0], bb[0], pA, 0);
    // stage 2 (all images)
    offcv3_kernel<<<dim3(128,5), 256, OC_SMEM>>>(xsA, 1);
    sg7_kernel<<<dim3(128,5), 512, SG7_SMEM>>>(xsA, cb[1], 1, 1);
    normrelu2_kernel<<<dim3(HW*C/256,5), 256>>>(bg[1], bb[1], pB, 1);
    // projections + final LN
    projH_kernel<<<dim3(128,3,5), 512, PJ_SMEM>>>(pB, xs0, outp);
    ln_kernel<<<768*Hh, 128>>>(outp, lnw, lnb);
}

// round 11
// speedup vs baseline: 3.1023x; 1.0840x over previous
#include <cuda_runtime.h>
#include <cuda_bf16.h>
#include <cstdint>

#define Hh 128
#define Ww 128
#define HW 16384
#define C 128
#define KK 9
#define EPS 1e-5f
#define NIMG 5

struct Ptr5 { const float* p[NIMG]; };

// ---------------- scratch (device globals; no runtime alloc) ----------------
__device__ float g_bufA[NIMG*HW*C];
__device__ float g_bufB[NIMG*HW*C];
__device__ float g_pre[NIMG*HW*C];
__device__ float g_offs[NIMG*HW*18];
__device__ float g_maskb[NIMG*HW*9];
__device__ uint32_t g_wtPh[2][KK*4*128*16];   // [b][k][cc][co][pair] bf16x2 hi
__device__ uint32_t g_wtPl[2][KK*4*128*16];
__device__ uint32_t g_effPh[2][KK*4*32*16];   // [b][k][cc][j][pair] bf16x2 hi
__device__ uint32_t g_effPl[2][KK*4*32*16];
__device__ float g_effb[2][32];
__device__ uint32_t g_pjH[1280*128];          // proj weights bf16x2 hi (K=256)
__device__ uint32_t g_pjL[1280*128];
__device__ float g_sumA[2*NIMG*128];
__device__ float g_sqA[2*NIMG*128];

__constant__ int c_ncos[5]   = {20,80,150,210,308};
__constant__ int c_pjbase[5] = {0,128,256,512,896};
__constant__ int c_coff[5]   = {0,20,100,250,460};
__constant__ int c_ccend[5]  = {4,4,8,8,8};

// ---------------- helpers ----------------
__device__ __forceinline__ uint32_t smem_u32(const void* p){
    uint32_t a;
    asm("{ .reg .u64 t; cvta.to.shared.u64 t, %1; cvt.u32.u64 %0, t; }" : "=r"(a) : "l"(p));
    return a;
}
__device__ __forceinline__ void bsplit2(float2 v, uint32_t &hp, uint32_t &lp_){
    __nv_bfloat162 h2 = __float22bfloat162_rn(v);
    float2 hf = __bfloat1622float2(h2);
    __nv_bfloat162 l2 = __float22bfloat162_rn(make_float2(v.x - hf.x, v.y - hf.y));
    hp = *reinterpret_cast<uint32_t*>(&h2);
    lp_ = *reinterpret_cast<uint32_t*>(&l2);
}
__device__ __forceinline__ void mma_bf16(float* d, uint32_t a0,uint32_t a1,uint32_t a2,uint32_t a3,
                                         uint32_t b0, uint32_t b1){
    asm volatile("mma.sync.aligned.m16n8k16.row.col.f32.bf16.bf16.f32 "
        "{%0,%1,%2,%3}, {%4,%5,%6,%7}, {%8,%9}, {%0,%1,%2,%3};"
        : "+f"(d[0]),"+f"(d[1]),"+f"(d[2]),"+f"(d[3])
        : "r"(a0),"r"(a1),"r"(a2),"r"(a3),"r"(b0),"r"(b1));
}
#define LDSM4(r, addr) \
    asm volatile("ldmatrix.sync.aligned.m8n8.x4.shared.b16 {%0,%1,%2,%3}, [%4];" \
        : "=r"((r)[0]),"=r"((r)[1]),"=r"((r)[2]),"=r"((r)[3]) : "r"(addr))
#define LDSM2(r, addr) \
    asm volatile("ldmatrix.sync.aligned.m8n8.x2.shared.b16 {%0,%1}, [%2];" \
        : "=r"((r)[0]),"=r"((r)[1]) : "r"(addr))

// 3-pass bf16-split MMA over one K=32 chunk via ldmatrix.
// aH/aL/bH/bL are per-thread smem byte-addresses with the lane pattern baked in:
//   aPat = sb + ((warpM*32 + (g&1)*8 + lr)*20 + (g>>1)*4)*4     (g=lane>>3, lr=lane&7)
//   bPat = sb + ((warpN*32 + lr)*20 + (g&1)*4)*4
// Strides: A mt: +1280B (16 rows x 80B); ks: +32B; B nt: +640B (8 rows x 80B).
__device__ __forceinline__ void mma_chunk3L(float d[2][4][4],
    uint32_t aH, uint32_t aL, uint32_t bH, uint32_t bL){
#pragma unroll
    for (int ks=0; ks<2; ks++){
        uint32_t ah[2][4], al[2][4];
        LDSM4(ah[0], aH + ks*32);
        LDSM4(ah[1], aH + 1280 + ks*32);
        LDSM4(al[0], aL + ks*32);
        LDSM4(al[1], aL + 1280 + ks*32);
        uint32_t bh[4][2];
#pragma unroll
        for (int nt=0;nt<4;nt++){
            LDSM2(bh[nt], bH + nt*640 + ks*32);
            mma_bf16(d[0][nt], ah[0][0],ah[0][1],ah[0][2],ah[0][3], bh[nt][0],bh[nt][1]);
            mma_bf16(d[1][nt], ah[1][0],ah[1][1],ah[1][2],ah[1][3], bh[nt][0],bh[nt][1]);
        }
#pragma unroll
        for (int nt=0;nt<4;nt++){
            uint32_t bl[2];
            LDSM2(bl, bL + nt*640 + ks*32);
            mma_bf16(d[0][nt], ah[0][0],ah[0][1],ah[0][2],ah[0][3], bl[0],bl[1]);
            mma_bf16(d[1][nt], ah[1][0],ah[1][1],ah[1][2],ah[1][3], bl[0],bl[1]);
        }
#pragma unroll
        for (int nt=0;nt<4;nt++){
            mma_bf16(d[0][nt], al[0][0],al[0][1],al[0][2],al[0][3], bh[nt][0],bh[nt][1]);
            mma_bf16(d[1][nt], al[1][0],al[1][1],al[1][2],al[1][3], bh[nt][0],bh[nt][1]);
        }
    }
}

// ---------------- prep kernels ----------------
__global__ void prep_wtP_kernel(const float* __restrict__ cw0, const float* __restrict__ cw1){
    int idx = blockIdx.x*blockDim.x + threadIdx.x;
    if (idx >= KK*4*128*16) return;
    int pr = idx & 15, co = (idx>>4)&127, cc = (idx>>11)&3, k = idx>>13;
    int ci0 = cc*32 + pr*2;
    uint32_t hp, lp;
    bsplit2(make_float2(cw0[(co*C+ci0)*KK + k], cw0[(co*C+ci0+1)*KK + k]), hp, lp);
    g_wtPh[0][idx]=hp; g_wtPl[0][idx]=lp;
    bsplit2(make_float2(cw1[(co*C+ci0)*KK + k], cw1[(co*C+ci0+1)*KK + k]), hp, lp);
    g_wtPh[1][idx]=hp; g_wtPl[1][idx]=lp;
}

__global__ void prep_effP_kernel(const float* __restrict__ cw, const float* __restrict__ ow,
                                 const float* __restrict__ mw, const float* __restrict__ cb, int b){
    int idx = blockIdx.x*blockDim.x + threadIdx.x;
    if (idx >= KK*4*32*16) return;
    int pr = idx&15, j = (idx>>4)&31, cc=(idx>>9)&3, k=idx>>11;
    int ci0 = cc*32 + pr*2;
    float s0=0.f, s1=0.f;
    if (j < 27){
        const float* P = (j<18) ? (ow + j*C) : (mw + (j-18)*C);
        for (int co=0; co<C; co++){
            float p = P[co];
            s0 += p*cw[(co*C+ci0)*KK + k];
            s1 += p*cw[(co*C+ci0+1)*KK + k];
        }
    }
    uint32_t hp, lp;
    bsplit2(make_float2(s0,s1), hp, lp);
    g_effPh[b][idx]=hp; g_effPl[b][idx]=lp;
    if (idx < 32){
        float bbv = 0.f;
        if (idx < 27){
            const float* P = (idx<18) ? (ow + idx*C) : (mw + (idx-18)*C);
            for (int co=0; co<C; co++) bbv += P[co]*cb[co];
        }
        g_effb[b][idx] = bbv;
    }
}

__global__ void prep_pj_kernel(Ptr5 wa, Ptr5 wb){
    int idx = blockIdx.x*blockDim.x + threadIdx.x;
    if (idx >= 1280*128) return;
    int u = idx & 127, row = idx >> 7;
    int img = 0;
#pragma unroll
    for (int i=1;i<5;i++) if (row >= c_pjbase[i]) img = i;
    int lco = row - c_pjbase[img];
    float v0=0.f, v1=0.f;
    if (lco < c_ncos[img]){
        if (u < 64){
            const float* w = wa.p[img];
            v0 = w[lco*C + u*2]; v1 = w[lco*C + u*2+1];
        } else {
            const float* w = wb.p[img];
            if (w){ v0 = w[lco*C + (u-64)*2]; v1 = w[lco*C + (u-64)*2+1]; }
        }
    }
    uint32_t hp, lp;
    bsplit2(make_float2(v0,v1), hp, lp);
    g_pjH[idx]=hp; g_pjL[idx]=lp;
}

__global__ void zero_sums_kernel(){
    int t = blockIdx.x*blockDim.x + threadIdx.x;
    if (t < 2*NIMG*128){ g_sumA[t]=0.f; g_sqA[t]=0.f; }
}

// ---------------- offsets conv via bf16 3-pass HMMA (PROVEN R7 version) ----------------
#define OC_SMEM (25560*4)
__global__ __launch_bounds__(256) void offcv3_kernel(Ptr5 xs, int b){
    extern __shared__ uint32_t su[];
    uint32_t* RH = su;
    uint32_t* RL = su + 7020;
    uint32_t* BOH = su + 14040;
    uint32_t* BOL = su + 19800;
    const int tid = threadIdx.x;
    const int h0 = blockIdx.x, img = blockIdx.y, pb = h0*128;
    const float* x = xs.p[img];
    float* offs = g_offs + (size_t)img*HW*18;
    float* mkb  = g_maskb + (size_t)img*HW*9;
    const int wid = tid>>5, lane = tid&31, lg = lane>>2, lc = lane&3;
    float d[4][4];
#pragma unroll
    for (int nt=0;nt<4;nt++)
#pragma unroll
        for (int i=0;i<4;i++) d[nt][i]=0.f;

    for (int cc=0; cc<4; cc++){
        __syncthreads();
#pragma unroll
        for (int t=0;t<2;t++){
            int idx = tid + t*256;
            if (idx < 384){
                int r = idx>>7, px = idx&127;
                int hh = h0 + r - 1;
                uint32_t base = (uint32_t)(r*130 + px + 1)*18;
                if (hh>=0 && hh<Hh){
                    const float4* src = (const float4*)(x + (((hh<<7)+px)<<7) + cc*32);
#pragma unroll
                    for (int i=0;i<8;i++){
                        float4 v = src[i];
                        uint32_t h0p,l0p,h1p,l1p;
                        bsplit2(make_float2(v.x,v.y), h0p,l0p);
                        bsplit2(make_float2(v.z,v.w), h1p,l1p);
                        *(uint2*)(RH + base + i*2) = make_uint2(h0p,h1p);
                        *(uint2*)(RL + base + i*2) = make_uint2(l0p,l1p);
                    }
                } else {
#pragma unroll
                    for (int i=0;i<8;i++){
                        *(uint2*)(RH + base + i*2) = make_uint2(0u,0u);
                        *(uint2*)(RL + base + i*2) = make_uint2(0u,0u);
                    }
                }
            }
        }
        if (tid < 96){
            int slot = tid>>4, pr = tid&15;
            int r = slot>>1, side = slot&1;
            uint32_t base = (uint32_t)(r*130 + (side?129:0))*18;
            RH[base+pr]=0u; RL[base+pr]=0u;
        }
#pragma unroll
        for (int t=0;t<18;t++){
            int idx = tid + t*256;
            int k = idx>>9, rr = idx & 511;
            int j = rr>>4, pr = rr&15;
            uint32_t gidx = (uint32_t)((k*4+cc)<<9) + (uint32_t)rr;
            BOH[(uint32_t)(k*32+j)*20 + pr] = g_effPh[b][gidx];
            BOL[(uint32_t)(k*32+j)*20 + pr] = g_effPl[b][gidx];
        }
        __syncthreads();
        for (int k=0;k<KK;k++){
            int ky = k/3, kx = k - ky*3 - 1;
#pragma unroll
            for (int ks=0; ks<2; ks++){
                uint32_t row = (uint32_t)(wid*16 + lg + kx + 1);
                uint32_t abase = ((uint32_t)ky*130 + row)*18 + ks*8 + lc;
                uint32_t ah0 = RH[abase],      ah1 = RH[abase + 144];
                uint32_t ah2 = RH[abase + 4],  ah3 = RH[abase + 148];
                uint32_t al0 = RL[abase],      al1 = RL[abase + 144];
                uint32_t al2 = RL[abase + 4],  al3 = RL[abase + 148];
#pragma unroll
                for (int nt=0;nt<4;nt++){
                    uint32_t bb = (uint32_t)(k*32 + nt*8 + lg)*20 + ks*8 + lc;
                    uint32_t b0 = BOH[bb], b1 = BOH[bb+4];
                    mma_bf16(d[nt], ah0,ah1,ah2,ah3, b0,b1);
                }
#pragma unroll
                for (int nt=0;nt<4;nt++){
                    uint32_t bb = (uint32_t)(k*32 + nt*8 + lg)*20 + ks*8 + lc;
                    uint32_t b0 = BOL[bb], b1 = BOL[bb+4];
                    mma_bf16(d[nt], ah0,ah1,ah2,ah3, b0,b1);
                }
#pragma unroll
                for (int nt=0;nt<4;nt++){
                    uint32_t bb = (uint32_t)(k*32 + nt*8 + lg)*20 + ks*8 + lc;
                    uint32_t b0 = BOH[bb], b1 = BOH[bb+4];
                    mma_bf16(d[nt], al0,al1,al2,al3, b0,b1);
                }
            }
        }
    }
    __syncthreads();
    float* Vs = (float*)su;  // [128][33]
#pragma unroll
    for (int nt=0;nt<4;nt++){
        int col = nt*8 + lc*2;
        int r0 = wid*16 + lg;
        Vs[r0*33 + col]       = d[nt][0] + g_effb[b][col];
        Vs[r0*33 + col + 1]   = d[nt][1] + g_effb[b][col+1];
        Vs[(r0+8)*33 + col]   = d[nt][2] + g_effb[b][col];
        Vs[(r0+8)*33 + col+1] = d[nt][3] + g_effb[b][col+1];
    }
    __syncthreads();
    if (tid < 128){
        int p = pb + tid;
        const float* v = Vs + tid*33;
#pragma unroll
        for (int j=0;j<18;j++) offs[p*18+j] = v[j];
        float mx = v[18];
#pragma unroll
        for (int j=19;j<27;j++) mx = fmaxf(mx, v[j]);
        float e[9]; float smv = 0.f;
#pragma unroll
        for (int j=0;j<9;j++){ e[j] = expf(v[18+j]-mx); smv += e[j]; }
        float inv = 1.f/smv;
#pragma unroll
        for (int j=0;j<9;j++) mkb[p*9+j] = e[j]*inv;
    }
}

// ---------------- pipelined sample-GEMM (q8 gather + ldmatrix fragments) ----------------
#define SGB 2560
#define SG7_SMEM (8*SGB*4)   // 81920 B
__global__ __launch_bounds__(512,1) void sg7_kernel(Ptr5 xs, const float* __restrict__ cbv,
                                                    int b, int s){
    extern __shared__ uint32_t su[];
    uint32_t* AHb[2]={su,         su + SGB};
    uint32_t* ALb[2]={su + 2*SGB, su + 3*SGB};
    uint32_t* BHb[2]={su + 4*SGB, su + 5*SGB};
    uint32_t* BLb[2]={su + 6*SGB, su + 7*SGB};
    const int tid = threadIdx.x;
    const int h0 = blockIdx.x, img = blockIdx.y, pb = h0*128;
    const float* x = xs.p[img];
    const float* offs = g_offs + (size_t)img*HW*18;
    const float* mkb  = g_maskb + (size_t)img*HW*9;
    const int q8 = tid & 7, pxA = tid >> 3;      // 2 px per thread: pxA, pxA+64
    const int cob = tid >> 2, qb = tid & 3;      // B staging roles
    const int wid = tid>>5, lane = tid&31, lg = lane>>2, lc = lane&3;
    const int warpM = wid&3, warpN = wid>>2;
    const int lr = lane&7, gg = lane>>3;

    // ldmatrix lane-pattern base addresses (byte)
    const uint32_t sb = smem_u32(su);
    const uint32_t aPat = sb + (uint32_t)(((warpM*32 + (gg&1)*8 + lr)*20 + (gg>>1)*4)*4);
    const uint32_t bPat = sb + (uint32_t)(((warpN*32 + lr)*20 + (gg&1)*4)*4);

    float d[2][4][4];
#pragma unroll
    for (int mt=0;mt<2;mt++)
#pragma unroll
        for (int nt=0;nt<4;nt++)
#pragma unroll
            for (int i=0;i<4;i++) d[mt][nt][i]=0.f;

    float w00[2],w01[2],w10[2],w11[2],mk[2];
    int roff[2][4];
    int pk = -1;
    float4 gr[2][4];
    uint4 wbh, wbl;

    auto compute_tap = [&](int k){
#pragma unroll
        for (int sl=0; sl<2; sl++){
            int px = pxA + sl*64;
            int p = pb + px;
            float offy = offs[p*18 + 2*k];
            float offx = offs[p*18 + 2*k + 1];
            mk[sl] = mkb[p*9 + k];
            float py  = (float)(h0 - 1 + k/3) + offy;
            float pxf = (float)(px - 1 + (k - (k/3)*3)) + offx;
            float y0f = floorf(py), x0f = floorf(pxf);
            int y0 = (int)y0f, x0i = (int)x0f;
            float wy1 = py - y0f, wy0 = 1.f - wy1;
            float wx1 = pxf - x0f, wx0 = 1.f - wx1;
            int y1 = y0+1, x1i = x0i+1;
            bool vy0 = (y0>=0)&(y0<Hh), vy1 = (y1>=0)&(y1<Hh);
            bool vx0 = (x0i>=0)&(x0i<Ww), vx1 = (x1i>=0)&(x1i<Ww);
            w00[sl] = (vy0&&vx0)? wy0*wx0 : 0.f;
            w01[sl] = (vy0&&vx1)? wy0*wx1 : 0.f;
            w10[sl] = (vy1&&vx0)? wy1*wx0 : 0.f;
            w11[sl] = (vy1&&vx1)? wy1*wx1 : 0.f;
            int y0c = min(max(y0,0),Hh-1), y1c = min(max(y1,0),Hh-1);
            int x0c = min(max(x0i,0),Ww-1), x1c = min(max(x1i,0),Ww-1);
            roff[sl][0] = ((y0c<<7)+x0c)<<7;
            roff[sl][1] = ((y0c<<7)+x1c)<<7;
            roff[sl][2] = ((y1c<<7)+x0c)<<7;
            roff[sl][3] = ((y1c<<7)+x1c)<<7;
        }
    };
    auto gather = [&](int it){
        int k = it>>2, cc = it&3;
        if (k != pk){ compute_tap(k); pk = k; }
        int cg = cc*32 + q8*4;
#pragma unroll
        for (int sl=0; sl<2; sl++)
#pragma unroll
            for (int c=0; c<4; c++)
                gr[sl][c] = *(const float4*)(x + roff[sl][c] + cg);
        uint32_t base = (uint32_t)(((k*4+cc)*128 + cob)*16 + qb*4);
        wbh = *(const uint4*)(&g_wtPh[b][base]);
        wbl = *(const uint4*)(&g_wtPl[b][base]);
    };
    auto store_stage = [&](int buf){
#pragma unroll
        for (int sl=0; sl<2; sl++){
            float4 a = gr[sl][0], b4 = gr[sl][1], c4 = gr[sl][2], e4 = gr[sl][3];
            float4 o;
            o.x = mk[sl]*(w00[sl]*a.x + w01[sl]*b4.x + w10[sl]*c4.x + w11[sl]*e4.x);
            o.y = mk[sl]*(w00[sl]*a.y + w01[sl]*b4.y + w10[sl]*c4.y + w11[sl]*e4.y);
            o.z = mk[sl]*(w00[sl]*a.z + w01[sl]*b4.z + w10[sl]*c4.z + w11[sl]*e4.z);
            o.w = mk[sl]*(w00[sl]*a.w + w01[sl]*b4.w + w10[sl]*c4.w + w11[sl]*e4.w);
            uint32_t h0p,l0p,h1p,l1p;
            bsplit2(make_float2(o.x,o.y), h0p,l0p);
            bsplit2(make_float2(o.z,o.w), h1p,l1p);
            uint32_t abase = (uint32_t)(pxA + sl*64)*20 + q8*2;
            *(uint2*)(AHb[buf]+abase) = make_uint2(h0p,h1p);
            *(uint2*)(ALb[buf]+abase) = make_uint2(l0p,l1p);
        }
        uint32_t bbase = (uint32_t)cob*20 + qb*4;
        *(uint4*)(BHb[buf]+bbase) = wbh;
        *(uint4*)(BLb[buf]+bbase) = wbl;
    };

    gather(0);
    for (int it=0; it<36; it++){
        int buf = it & 1;
        store_stage(buf);
        __syncthreads();
        if (it < 35) gather(it+1);
        uint32_t boff = (uint32_t)buf*(SGB*4);
        mma_chunk3L(d, aPat + boff, aPat + 2*(SGB*4) + boff,
                       bPat + 4*(SGB*4) + boff, bPat + 6*(SGB*4) + boff);
    }
    __syncthreads();

    // epilogue: bias + g_pre + fused stats
    float* Vs  = (float*)su;        // [128][132]
    float* Ps  = Vs + 16896;
    float* Ps2 = Ps + 512;
#pragma unroll
    for (int mt=0;mt<2;mt++){
        int r0 = warpM*32 + mt*16 + lg;
#pragma unroll
        for (int nt=0;nt<4;nt++){
            int co0 = warpN*32 + nt*8 + lc*2;
            float b0v = cbv[co0], b1v = cbv[co0+1];
            *(float2*)(Vs + r0*132 + co0)     = make_float2(d[mt][nt][0]+b0v, d[mt][nt][1]+b1v);
            *(float2*)(Vs + (r0+8)*132 + co0) = make_float2(d[mt][nt][2]+b0v, d[mt][nt][3]+b1v);
        }
    }
    __syncthreads();
    float* preo = g_pre + (size_t)img*HW*C;
#pragma unroll
    for (int t=0;t<32;t++){
        int idx = tid + t*512;
        int p2 = idx>>7, co = idx&127;
        preo[(pb+p2)*C + co] = Vs[p2*132 + co];
    }
    {
        int co = tid&127, qq = tid>>7;
        float S=0.f, Q=0.f;
#pragma unroll 8
        for (int i=0;i<32;i++){ float v = Vs[(qq*32+i)*132+co]; S += v; Q += v*v; }
        Ps[qq*128+co] = S; Ps2[qq*128+co] = Q;
        __syncthreads();
        if (tid < 128){
            float SS = Ps[tid]+Ps[128+tid]+Ps[256+tid]+Ps[384+tid];
            float QQ = Ps2[tid]+Ps2[128+tid]+Ps2[256+tid]+Ps2[384+tid];
            atomicAdd(&g_sumA[(s*NIMG+img)*128+tid], SS);
            atomicAdd(&g_sqA[(s*NIMG+img)*128+tid], QQ);
        }
    }
}

// ---------------- instance-norm apply ----------------
__global__ void normrelu2_kernel(const float* __restrict__ bg, const float* __restrict__ bb,
                                 float* __restrict__ outbase, int s){
    int img = blockIdx.y;
    int idx = blockIdx.x*blockDim.x + threadIdx.x;
    int c = idx & 127;
    float mu = g_sumA[(s*NIMG+img)*128+c] * (1.f/HW);
    float var = g_sqA[(s*NIMG+img)*128+c] * (1.f/HW) - mu*mu;
    float v = (g_pre[(size_t)img*HW*C + idx]-mu)*rsqrtf(var+EPS)*bg[c] + bb[c];
    outbase[(size_t)img*HW*C + idx] = fmaxf(v, 0.f);
}

// ---------------- projections via HMMA (K=256: xc || xp; NCC skip; ldmatrix) ----------------
#define PJ_SMEM (8*SGB*4)
__global__ __launch_bounds__(512,1) void projH_kernel(const float* __restrict__ xcbase, Ptr5 xps,
                                                      float* __restrict__ out){
    const int img = blockIdx.z;
    const int nco = c_ncos[img];
    const int ct = blockIdx.y;
    if (ct*128 >= nco) return;
    extern __shared__ uint32_t su[];
    uint32_t* AHb[2]={su,         su + SGB};
    uint32_t* ALb[2]={su + 2*SGB, su + 3*SGB};
    uint32_t* BHb[2]={su + 4*SGB, su + 5*SGB};
    uint32_t* BLb[2]={su + 6*SGB, su + 7*SGB};
    const int tid = threadIdx.x;
    const int h0 = blockIdx.x, pb = h0*128;
    const float* xc = xcbase + (size_t)img*HW*C;
    const float* xp = xps.p[img];
    const int px = tid>>2, q4 = tid&3;
    const int wid = tid>>5, lane = tid&31, lg = lane>>2, lc = lane&3;
    const int warpM = wid&3, warpN = wid>>2;
    const int rowbase = c_pjbase[img] + ct*128;
    const int NCC = c_ccend[img];
    const int lr = lane&7, gg = lane>>3;

    const uint32_t sb = smem_u32(su);
    const uint32_t aPat = sb + (uint32_t)(((warpM*32 + (gg&1)*8 + lr)*20 + (gg>>1)*4)*4);
    const uint32_t bPat = sb + (uint32_t)(((warpN*32 + lr)*20 + (gg&1)*4)*4);

    float d[2][4][4];
#pragma unroll
    for (int mt=0;mt<2;mt++)
#pragma unroll
        for (int nt=0;nt<4;nt++)
#pragma unroll
            for (int i=0;i<4;i++) d[mt][nt][i]=0.f;

    float4 gr[2];
    uint4 wbh, wbl;
    auto load_chunk = [&](int cc){
        const float* src = (cc<4) ? (xc + (size_t)(pb+px)*C + cc*32 + q4*8)
                                  : (xp + (size_t)(pb+px)*C + (cc-4)*32 + q4*8);
        gr[0] = ((const float4*)src)[0];
        gr[1] = ((const float4*)src)[1];
        uint32_t base = (uint32_t)((rowbase+px)*128 + cc*16 + q4*4);
        wbh = *(const uint4*)(&g_pjH[base]);
        wbl = *(const uint4*)(&g_pjL[base]);
    };
    auto store_stage = [&](int buf){
        uint32_t hh[4], ll[4];
        bsplit2(make_float2(gr[0].x,gr[0].y), hh[0], ll[0]);
        bsplit2(make_float2(gr[0].z,gr[0].w), hh[1], ll[1]);
        bsplit2(make_float2(gr[1].x,gr[1].y), hh[2], ll[2]);
        bsplit2(make_float2(gr[1].z,gr[1].w), hh[3], ll[3]);
        uint32_t abase = (uint32_t)px*20 + q4*4;
        *(uint4*)(AHb[buf]+abase) = make_uint4(hh[0],hh[1],hh[2],hh[3]);
        *(uint4*)(ALb[buf]+abase) = make_uint4(ll[0],ll[1],ll[2],ll[3]);
        *(uint4*)(BHb[buf]+abase) = wbh;
        *(uint4*)(BLb[buf]+abase) = wbl;
    };

    load_chunk(0); store_stage(0);
    __syncthreads();
    for (int cc=0; cc<NCC; cc++){
        if (cc < NCC-1) load_chunk(cc+1);
        uint32_t boff = (uint32_t)(cc&1)*(SGB*4);
        mma_chunk3L(d, aPat + boff, aPat + 2*(SGB*4) + boff,
                       bPat + 4*(SGB*4) + boff, bPat + 6*(SGB*4) + boff);
        if (cc < NCC-1) store_stage((cc+1)&1);
        __syncthreads();
    }

    float* Vs = (float*)su;   // [128][132]
#pragma unroll
    for (int mt=0;mt<2;mt++){
        int r0 = warpM*32 + mt*16 + lg;
#pragma unroll
        for (int nt=0;nt<4;nt++){
            int co0 = warpN*32 + nt*8 + lc*2;
            *(float2*)(Vs + r0*132 + co0)     = make_float2(d[mt][nt][0], d[mt][nt][1]);
            *(float2*)(Vs + (r0+8)*132 + co0) = make_float2(d[mt][nt][2], d[mt][nt][3]);
        }
    }
    __syncthreads();
    {
        int co = tid>>2, sub = tid&3;
        int cog = ct*128 + co;
        if (cog < nco){
            float* dst = out + (size_t)(c_coff[img]+cog)*HW + pb + sub*32;
#pragma unroll
            for (int j=0;j<8;j++){
                int r = sub*32 + j*4;
                float4 o = make_float4(Vs[r*132+co], Vs[(r+1)*132+co],
                                       Vs[(r+2)*132+co], Vs[(r+3)*132+co]);
                *(float4*)(dst + j*4) = o;
            }
        }
    }
}

// ---------------- final layernorm over W ----------------
__global__ __launch_bounds__(128) void ln_kernel(float* __restrict__ o, const float* __restrict__ lnw,
                                                 const float* __restrict__ lnb){
    __shared__ float ss[4], ssq[4];
    int row = blockIdx.x;
    float* r = o + (size_t)row*128;
    int t = threadIdx.x;
    float v = r[t];
    float s = v, sq = v*v;
#pragma unroll
    for (int off=16; off; off>>=1){
        s  += __shfl_down_sync(0xffffffffu, s, off);
        sq += __shfl_down_sync(0xffffffffu, sq, off);
    }
    int wid = t >> 5, lane = t & 31;
    if (lane==0){ ss[wid]=s; ssq[wid]=sq; }
    __syncthreads();
    float S  = ss[0]+ss[1]+ss[2]+ss[3];
    float SQ = ssq[0]+ssq[1]+ssq[2]+ssq[3];
    float mu = S*(1.f/128.f);
    float var = SQ*(1.f/128.f) - mu*mu;
    r[t] = (v-mu)*rsqrtf(var+EPS)*lnw[t] + lnb[t];
}

// ---------------- host orchestration ----------------
extern "C" void kernel_launch(void* const* d_in, const int* in_sizes, int n_in,
                              void* d_out, int out_size){
    (void)in_sizes; (void)n_in; (void)out_size;
    const float* x[5];
    for (int i=0;i<5;i++) x[i] = (const float*)d_in[i];
    const float* cw[2] = {(const float*)d_in[5],  (const float*)d_in[11]};
    const float* cb[2] = {(const float*)d_in[6],  (const float*)d_in[12]};
    const float* ow[2] = {(const float*)d_in[7],  (const float*)d_in[13]};
    const float* mw[2] = {(const float*)d_in[8],  (const float*)d_in[14]};
    const float* bg[2] = {(const float*)d_in[9],  (const float*)d_in[15]};
    const float* bb[2] = {(const float*)d_in[10], (const float*)d_in[16]};
    const float* pwa[5] = {(const float*)d_in[17], (const float*)d_in[18], (const float*)d_in[19],
                           (const float*)d_in[21], (const float*)d_in[23]};
    const float* pwb[5] = {nullptr, nullptr, (const float*)d_in[20],
                           (const float*)d_in[22], (const float*)d_in[24]};
    const float* lnw = (const float*)d_in[25];
    const float* lnb = (const float*)d_in[26];
    float* outp = (float*)d_out;

    float *pA=nullptr, *pB=nullptr;
    cudaGetSymbolAddress((void**)&pA, g_bufA);
    cudaGetSymbolAddress((void**)&pB, g_bufB);

    Ptr5 xs0, xsA, wav, wbv;
    for (int i=0;i<5;i++){
        xs0.p[i] = x[i];
        xsA.p[i] = pA + (size_t)i*HW*C;
        wav.p[i] = pwa[i];
        wbv.p[i] = pwb[i];
    }

    cudaFuncSetAttribute(offcv3_kernel, cudaFuncAttributeMaxDynamicSharedMemorySize, OC_SMEM);
    cudaFuncSetAttribute(sg7_kernel, cudaFuncAttributeMaxDynamicSharedMemorySize, SG7_SMEM);
    cudaFuncSetAttribute(projH_kernel, cudaFuncAttributeMaxDynamicSharedMemorySize, PJ_SMEM);

    prep_wtP_kernel<<<(KK*4*128*16+255)/256, 256>>>(cw[0], cw[1]);
    prep_effP_kernel<<<(KK*4*32*16+255)/256, 256>>>(cw[0], ow[0], mw[0], cb[0], 0);
    prep_effP_kernel<<<(KK*4*32*16+255)/256, 256>>>(cw[1], ow[1], mw[1], cb[1], 1);
    prep_pj_kernel<<<(1280*128+255)/256, 256>>>(wav, wbv);
    zero_sums_kernel<<<5, 256>>>();

    // stage 1 (all images)
    offcv3_kernel<<<dim3(128,5), 256, OC_SMEM>>>(xs0, 0);
    sg7_kernel<<<dim3(128,5), 512, SG7_SMEM>>>(xs0, cb[0], 0, 0);
    normrelu2_kernel<<<dim3(HW*C/256,5), 256>>>(bg[0], bb[0], pA, 0);
    // stage 2 (all images)
    offcv3_kernel<<<dim3(128,5), 256, OC_SMEM>>>(xsA, 1);
    sg7_kernel<<<dim3(128,5), 512, SG7_SMEM>>>(xsA, cb[1], 1, 1);
    normrelu2_kernel<<<dim3(HW*C/256,5), 256>>>(bg[1], bb[1], pB, 1);
    // projections + final LN
    projH_kernel<<<dim3(128,3,5), 512, PJ_SMEM>>>(pB, xs0, outp);
    ln_kernel<<<768*Hh, 128>>>(outp, lnw, lnb);
}